// round 6
// baseline (speedup 1.0000x reference)
#include <cuda_runtime.h>
#include <math.h>

#define Bb 8
#define HH 64
#define WWw 64
#define CC 512
#define GG 32
#define CGc (CC/GG)          /* 16 */
#define NTOK (HH*WWw)        /* 4096 */
#define EPSV 1e-5f

// ---------------- scratch (device globals; no runtime allocation) ----------------
__device__ float g_h [(size_t)Bb*NTOK*CC];
__device__ float g_q [(size_t)Bb*NTOK*CC];
__device__ float g_k [(size_t)Bb*NTOK*CC];
__device__ float g_v [(size_t)Bb*NTOK*CC];
__device__ float g_ao[(size_t)Bb*NTOK*CC];
__device__ float g_s [(size_t)Bb*NTOK*NTOK];   // 512 MB scores

// ---------------- GroupNorm ----------------
// one block per (batch, group); reduce over NTOK*CGc = 65536 elems
__global__ void gn_kernel(const float* __restrict__ x,
                          const float* __restrict__ sc,
                          const float* __restrict__ bi,
                          float* __restrict__ h) {
    int b = blockIdx.x / GG, g = blockIdx.x % GG;
    const float* xp = x + (size_t)b*NTOK*CC + g*CGc;
    float*       hp = h + (size_t)b*NTOK*CC + g*CGc;
    int tid = threadIdx.x;

    float s = 0.f, ss = 0.f;
    for (int i = tid; i < NTOK*CGc; i += 256) {
        int n = i >> 4, c = i & 15;
        float v = xp[(size_t)n*CC + c];
        s += v; ss += v*v;
    }
    __shared__ float r1[256], r2[256];
    r1[tid] = s; r2[tid] = ss; __syncthreads();
    for (int o = 128; o > 0; o >>= 1) {
        if (tid < o) { r1[tid] += r1[tid+o]; r2[tid] += r2[tid+o]; }
        __syncthreads();
    }
    const float invn = 1.f / (float)(NTOK*CGc);
    float mean = r1[0] * invn;
    float var  = r2[0] * invn - mean*mean;
    float inv  = rsqrtf(var + EPSV);

    for (int i = tid; i < NTOK*CGc; i += 256) {
        int n = i >> 4, c = i & 15;
        float v = xp[(size_t)n*CC + c];
        hp[(size_t)n*CC + c] = (v - mean) * inv * sc[g*CGc + c] + bi[g*CGc + c];
    }
}

// ---------------- tiled fp32 GEMM ----------------
// C[M,N] = alpha * A[M,K] @ op(B) + bias + resid
// TRANSB=false: B is [K,N] row-major.  TRANSB=true: B is [N,K] row-major (S = Q K^T).
#define BM 128
#define BN 128
#define BKK 16

template<bool TRANSB>
__global__ __launch_bounds__(256, 2)
void gemm_kernel(const float* __restrict__ A, int lda, long long sA,
                 const float* __restrict__ Bm, int ldb, long long sB,
                 float* __restrict__ Cm, int ldc, long long sC,
                 const float* __restrict__ bias,
                 const float* __restrict__ resid,
                 float alpha, int M, int Nc, int K) {
    __shared__ float As[BKK][BM+4];
    __shared__ float Bs[BKK][BN+4];

    const float* Ab = A  + (size_t)blockIdx.z * sA;
    const float* Bp = Bm + (size_t)blockIdx.z * sB;
    float*       Cb = Cm + (size_t)blockIdx.z * sC;
    const float* Rb = resid;   // only used when gridDim.z==1

    int m0 = blockIdx.y * BM, n0 = blockIdx.x * BN;
    int tid = threadIdx.x;
    int tx = tid & 15, ty = tid >> 4;

    float acc[8][8];
    #pragma unroll
    for (int i = 0; i < 8; i++)
        #pragma unroll
        for (int j = 0; j < 8; j++) acc[i][j] = 0.f;

    for (int k0 = 0; k0 < K; k0 += BKK) {
        // load A tile 128x16 (K contiguous per lane -> coalesced)
        #pragma unroll
        for (int t = 0; t < 2; t++) {
            int l  = tid + t*256;
            int m  = l >> 2;
            int kq = (l & 3) << 2;
            float4 v = *(const float4*)(Ab + (size_t)(m0+m)*lda + (k0+kq));
            As[kq+0][m] = v.x; As[kq+1][m] = v.y; As[kq+2][m] = v.z; As[kq+3][m] = v.w;
        }
        if (TRANSB) {
            #pragma unroll
            for (int t = 0; t < 2; t++) {
                int l  = tid + t*256;
                int n  = l >> 2;
                int kq = (l & 3) << 2;
                float4 v = *(const float4*)(Bp + (size_t)(n0+n)*ldb + (k0+kq));
                Bs[kq+0][n] = v.x; Bs[kq+1][n] = v.y; Bs[kq+2][n] = v.z; Bs[kq+3][n] = v.w;
            }
        } else {
            #pragma unroll
            for (int t = 0; t < 2; t++) {
                int l  = tid + t*256;
                int k  = l >> 5;
                int nq = (l & 31) << 2;
                *(float4*)&Bs[k][nq] = *(const float4*)(Bp + (size_t)(k0+k)*ldb + n0 + nq);
            }
        }
        __syncthreads();

        #pragma unroll
        for (int kk = 0; kk < BKK; kk++) {
            float a[8], b[8];
            *(float4*)&a[0] = *(const float4*)&As[kk][ty*4];
            *(float4*)&a[4] = *(const float4*)&As[kk][ty*4 + 64];
            *(float4*)&b[0] = *(const float4*)&Bs[kk][tx*4];
            *(float4*)&b[4] = *(const float4*)&Bs[kk][tx*4 + 64];
            #pragma unroll
            for (int i = 0; i < 8; i++)
                #pragma unroll
                for (int j = 0; j < 8; j++)
                    acc[i][j] = fmaf(a[i], b[j], acc[i][j]);
        }
        __syncthreads();
    }

    // epilogue: row(i) = m0 + ty*4 + (i%4) + (i/4)*64 ; col(j) analogous with tx
    #pragma unroll
    for (int i = 0; i < 8; i++) {
        int m = m0 + (ty<<2) + (i & 3) + ((i >> 2) << 6);
        size_t crow = (size_t)m * ldc;
        #pragma unroll
        for (int jh = 0; jh < 2; jh++) {
            int n = n0 + (tx<<2) + (jh << 6);
            float4 o;
            o.x = acc[i][jh*4+0] * alpha;
            o.y = acc[i][jh*4+1] * alpha;
            o.z = acc[i][jh*4+2] * alpha;
            o.w = acc[i][jh*4+3] * alpha;
            if (bias) {
                o.x += bias[n];   o.y += bias[n+1];
                o.z += bias[n+2]; o.w += bias[n+3];
            }
            if (Rb) {
                float4 r = *(const float4*)(Rb + crow + n);
                o.x += r.x; o.y += r.y; o.z += r.z; o.w += r.w;
            }
            *(float4*)(Cb + crow + n) = o;
        }
    }
}

// ---------------- row softmax (one block per row, values cached in regs) ----------------
__global__ void softmax_kernel(float* __restrict__ s) {
    size_t row = blockIdx.x;
    float* p = s + row * (size_t)NTOK;
    int tid = threadIdx.x;

    float vals[16];
    float m = -3.4e38f;
    #pragma unroll
    for (int t = 0; t < 16; t++) {
        vals[t] = p[tid + t*256];
        m = fmaxf(m, vals[t]);
    }
    __shared__ float red[256];
    red[tid] = m; __syncthreads();
    for (int o = 128; o > 0; o >>= 1) {
        if (tid < o) red[tid] = fmaxf(red[tid], red[tid+o]);
        __syncthreads();
    }
    m = red[0]; __syncthreads();

    float sum = 0.f;
    #pragma unroll
    for (int t = 0; t < 16; t++) {
        vals[t] = __expf(vals[t] - m);
        sum += vals[t];
    }
    red[tid] = sum; __syncthreads();
    for (int o = 128; o > 0; o >>= 1) {
        if (tid < o) red[tid] += red[tid+o];
        __syncthreads();
    }
    float r = 1.f / red[0];
    #pragma unroll
    for (int t = 0; t < 16; t++) p[tid + t*256] = vals[t] * r;
}

// ---------------- launch ----------------
extern "C" void kernel_launch(void* const* d_in, const int* in_sizes, int n_in,
                              void* d_out, int out_size) {
    const float* x  = (const float*)d_in[0];
    const float* gs = (const float*)d_in[1];
    const float* gb = (const float*)d_in[2];
    const float* wq = (const float*)d_in[3];
    const float* bq = (const float*)d_in[4];
    const float* wk = (const float*)d_in[5];
    const float* bk = (const float*)d_in[6];
    const float* wv = (const float*)d_in[7];
    const float* bv = (const float*)d_in[8];
    const float* wo = (const float*)d_in[9];
    const float* bo = (const float*)d_in[10];
    float* out = (float*)d_out;

    float *h, *q, *k, *v, *ao, *s;
    cudaGetSymbolAddress((void**)&h,  g_h);
    cudaGetSymbolAddress((void**)&q,  g_q);
    cudaGetSymbolAddress((void**)&k,  g_k);
    cudaGetSymbolAddress((void**)&v,  g_v);
    cudaGetSymbolAddress((void**)&ao, g_ao);
    cudaGetSymbolAddress((void**)&s,  g_s);

    const long long sNC = (long long)NTOK * CC;   // per-batch q/k/v stride
    const long long sNN = (long long)NTOK * NTOK; // per-batch scores stride
    const int Mtot = Bb * NTOK;                   // 32768
    const float inv_sqrt_c = 0.044194173824159216f; // 512^-0.5

    // 1) GroupNorm
    gn_kernel<<<Bb*GG, 256>>>(x, gs, gb, h);

    // 2) Q, K, V projections: [32768,512] @ [512,512] + bias
    dim3 gproj(CC/BN, Mtot/BM, 1);
    gemm_kernel<false><<<gproj, 256>>>(h, CC, 0, wq, CC, 0, q, CC, 0, bq, nullptr, 1.f, Mtot, CC, CC);
    gemm_kernel<false><<<gproj, 256>>>(h, CC, 0, wk, CC, 0, k, CC, 0, bk, nullptr, 1.f, Mtot, CC, CC);
    gemm_kernel<false><<<gproj, 256>>>(h, CC, 0, wv, CC, 0, v, CC, 0, bv, nullptr, 1.f, Mtot, CC, CC);

    // 3) scores = alpha * Q @ K^T  (batched over z)
    dim3 gsc(NTOK/BN, NTOK/BM, Bb);
    gemm_kernel<true><<<gsc, 256>>>(q, CC, sNC, k, CC, sNC, s, NTOK, sNN,
                                    nullptr, nullptr, inv_sqrt_c, NTOK, NTOK, CC);

    // 4) softmax over keys
    softmax_kernel<<<Bb*NTOK, 256>>>(s);

    // 5) attn @ V  (batched)
    dim3 gav(CC/BN, NTOK/BM, Bb);
    gemm_kernel<false><<<gav, 256>>>(s, NTOK, sNN, v, CC, sNC, ao, CC, sNC,
                                     nullptr, nullptr, 1.f, NTOK, CC, NTOK);

    // 6) output projection + bias + residual -> d_out
    gemm_kernel<false><<<gproj, 256>>>(ao, CC, 0, wo, CC, 0, out, CC, 0, bo, x, 1.f, Mtot, CC, CC);
}

// round 7
// speedup vs baseline: 1.0011x; 1.0011x over previous
#include <cuda_runtime.h>
#include <math.h>

#define Bb 8
#define HH 64
#define WWw 64
#define CC 512
#define GG 32
#define CGc (CC/GG)          /* 16 */
#define NTOK (HH*WWw)        /* 4096 */
#define EPSV 1e-5f

// ---------------- scratch (device globals; no runtime allocation) ----------------
__device__ float g_h [(size_t)Bb*NTOK*CC];
__device__ float g_q [(size_t)Bb*NTOK*CC];
__device__ float g_k [(size_t)Bb*NTOK*CC];
__device__ float g_v [(size_t)Bb*NTOK*CC];
__device__ float g_ao[(size_t)Bb*NTOK*CC];
__device__ float g_s [(size_t)Bb*NTOK*NTOK];   // 512 MB scores

// ---------------- GroupNorm ----------------
// one block per (batch, group); reduce over NTOK*CGc = 65536 elems
__global__ void gn_kernel(const float* __restrict__ x,
                          const float* __restrict__ sc,
                          const float* __restrict__ bi,
                          float* __restrict__ h) {
    int b = blockIdx.x / GG, g = blockIdx.x % GG;
    const float* xp = x + (size_t)b*NTOK*CC + g*CGc;
    float*       hp = h + (size_t)b*NTOK*CC + g*CGc;
    int tid = threadIdx.x;

    float s = 0.f, ss = 0.f;
    for (int i = tid; i < NTOK*CGc; i += 256) {
        int n = i >> 4, c = i & 15;
        float v = xp[(size_t)n*CC + c];
        s += v; ss += v*v;
    }
    __shared__ float r1[256], r2[256];
    r1[tid] = s; r2[tid] = ss; __syncthreads();
    for (int o = 128; o > 0; o >>= 1) {
        if (tid < o) { r1[tid] += r1[tid+o]; r2[tid] += r2[tid+o]; }
        __syncthreads();
    }
    const float invn = 1.f / (float)(NTOK*CGc);
    float mean = r1[0] * invn;
    float var  = r2[0] * invn - mean*mean;
    float inv  = rsqrtf(var + EPSV);

    for (int i = tid; i < NTOK*CGc; i += 256) {
        int n = i >> 4, c = i & 15;
        float v = xp[(size_t)n*CC + c];
        hp[(size_t)n*CC + c] = (v - mean) * inv * sc[g*CGc + c] + bi[g*CGc + c];
    }
}

// ---------------- tiled fp32 GEMM ----------------
// C[M,N] = alpha * A[M,K] @ op(B) + bias + resid
// TRANSB=false: B is [K,N] row-major.  TRANSB=true: B is [N,K] row-major (S = Q K^T).
#define BM 128
#define BN 128
#define BKK 16

template<bool TRANSB>
__global__ __launch_bounds__(256, 2)
void gemm_kernel(const float* __restrict__ A, int lda, long long sA,
                 const float* __restrict__ Bm, int ldb, long long sB,
                 float* __restrict__ Cm, int ldc, long long sC,
                 const float* __restrict__ bias,
                 const float* __restrict__ resid,
                 float alpha, int M, int Nc, int K) {
    __shared__ float As[BKK][BM+4];
    __shared__ float Bs[BKK][BN+4];

    const float* Ab = A  + (size_t)blockIdx.z * sA;
    const float* Bp = Bm + (size_t)blockIdx.z * sB;
    float*       Cb = Cm + (size_t)blockIdx.z * sC;
    const float* Rb = resid;   // only used when gridDim.z==1

    int m0 = blockIdx.y * BM, n0 = blockIdx.x * BN;
    int tid = threadIdx.x;
    int tx = tid & 15, ty = tid >> 4;

    float acc[8][8];
    #pragma unroll
    for (int i = 0; i < 8; i++)
        #pragma unroll
        for (int j = 0; j < 8; j++) acc[i][j] = 0.f;

    for (int k0 = 0; k0 < K; k0 += BKK) {
        // load A tile 128x16 (K contiguous per lane -> coalesced)
        #pragma unroll
        for (int t = 0; t < 2; t++) {
            int l  = tid + t*256;
            int m  = l >> 2;
            int kq = (l & 3) << 2;
            float4 v = *(const float4*)(Ab + (size_t)(m0+m)*lda + (k0+kq));
            As[kq+0][m] = v.x; As[kq+1][m] = v.y; As[kq+2][m] = v.z; As[kq+3][m] = v.w;
        }
        if (TRANSB) {
            #pragma unroll
            for (int t = 0; t < 2; t++) {
                int l  = tid + t*256;
                int n  = l >> 2;
                int kq = (l & 3) << 2;
                float4 v = *(const float4*)(Bp + (size_t)(n0+n)*ldb + (k0+kq));
                Bs[kq+0][n] = v.x; Bs[kq+1][n] = v.y; Bs[kq+2][n] = v.z; Bs[kq+3][n] = v.w;
            }
        } else {
            #pragma unroll
            for (int t = 0; t < 2; t++) {
                int l  = tid + t*256;
                int k  = l >> 5;
                int nq = (l & 31) << 2;
                *(float4*)&Bs[k][nq] = *(const float4*)(Bp + (size_t)(k0+k)*ldb + n0 + nq);
            }
        }
        __syncthreads();

        #pragma unroll
        for (int kk = 0; kk < BKK; kk++) {
            float a[8], b[8];
            *(float4*)&a[0] = *(const float4*)&As[kk][ty*4];
            *(float4*)&a[4] = *(const float4*)&As[kk][ty*4 + 64];
            *(float4*)&b[0] = *(const float4*)&Bs[kk][tx*4];
            *(float4*)&b[4] = *(const float4*)&Bs[kk][tx*4 + 64];
            #pragma unroll
            for (int i = 0; i < 8; i++)
                #pragma unroll
                for (int j = 0; j < 8; j++)
                    acc[i][j] = fmaf(a[i], b[j], acc[i][j]);
        }
        __syncthreads();
    }

    // epilogue: row(i) = m0 + ty*4 + (i%4) + (i/4)*64 ; col(j) analogous with tx
    #pragma unroll
    for (int i = 0; i < 8; i++) {
        int m = m0 + (ty<<2) + (i & 3) + ((i >> 2) << 6);
        size_t crow = (size_t)m * ldc;
        #pragma unroll
        for (int jh = 0; jh < 2; jh++) {
            int n = n0 + (tx<<2) + (jh << 6);
            float4 o;
            o.x = acc[i][jh*4+0] * alpha;
            o.y = acc[i][jh*4+1] * alpha;
            o.z = acc[i][jh*4+2] * alpha;
            o.w = acc[i][jh*4+3] * alpha;
            if (bias) {
                o.x += bias[n];   o.y += bias[n+1];
                o.z += bias[n+2]; o.w += bias[n+3];
            }
            if (Rb) {
                float4 r = *(const float4*)(Rb + crow + n);
                o.x += r.x; o.y += r.y; o.z += r.z; o.w += r.w;
            }
            *(float4*)(Cb + crow + n) = o;
        }
    }
}

// ---------------- row softmax (one block per row, values cached in regs) ----------------
__global__ void softmax_kernel(float* __restrict__ s) {
    size_t row = blockIdx.x;
    float* p = s + row * (size_t)NTOK;
    int tid = threadIdx.x;

    float vals[16];
    float m = -3.4e38f;
    #pragma unroll
    for (int t = 0; t < 16; t++) {
        vals[t] = p[tid + t*256];
        m = fmaxf(m, vals[t]);
    }
    __shared__ float red[256];
    red[tid] = m; __syncthreads();
    for (int o = 128; o > 0; o >>= 1) {
        if (tid < o) red[tid] = fmaxf(red[tid], red[tid+o]);
        __syncthreads();
    }
    m = red[0]; __syncthreads();

    float sum = 0.f;
    #pragma unroll
    for (int t = 0; t < 16; t++) {
        vals[t] = __expf(vals[t] - m);
        sum += vals[t];
    }
    red[tid] = sum; __syncthreads();
    for (int o = 128; o > 0; o >>= 1) {
        if (tid < o) red[tid] += red[tid+o];
        __syncthreads();
    }
    float r = 1.f / red[0];
    #pragma unroll
    for (int t = 0; t < 16; t++) p[tid + t*256] = vals[t] * r;
}

// ---------------- launch ----------------
extern "C" void kernel_launch(void* const* d_in, const int* in_sizes, int n_in,
                              void* d_out, int out_size) {
    const float* x  = (const float*)d_in[0];
    const float* gs = (const float*)d_in[1];
    const float* gb = (const float*)d_in[2];
    const float* wq = (const float*)d_in[3];
    const float* bq = (const float*)d_in[4];
    const float* wk = (const float*)d_in[5];
    const float* bk = (const float*)d_in[6];
    const float* wv = (const float*)d_in[7];
    const float* bv = (const float*)d_in[8];
    const float* wo = (const float*)d_in[9];
    const float* bo = (const float*)d_in[10];
    float* out = (float*)d_out;

    float *h, *q, *k, *v, *ao, *s;
    cudaGetSymbolAddress((void**)&h,  g_h);
    cudaGetSymbolAddress((void**)&q,  g_q);
    cudaGetSymbolAddress((void**)&k,  g_k);
    cudaGetSymbolAddress((void**)&v,  g_v);
    cudaGetSymbolAddress((void**)&ao, g_ao);
    cudaGetSymbolAddress((void**)&s,  g_s);

    const long long sNC = (long long)NTOK * CC;   // per-batch q/k/v stride
    const long long sNN = (long long)NTOK * NTOK; // per-batch scores stride
    const int Mtot = Bb * NTOK;                   // 32768
    const float inv_sqrt_c = 0.044194173824159216f; // 512^-0.5

    // 1) GroupNorm
    gn_kernel<<<Bb*GG, 256>>>(x, gs, gb, h);

    // 2) Q, K, V projections: [32768,512] @ [512,512] + bias
    dim3 gproj(CC/BN, Mtot/BM, 1);
    gemm_kernel<false><<<gproj, 256>>>(h, CC, 0, wq, CC, 0, q, CC, 0, bq, nullptr, 1.f, Mtot, CC, CC);
    gemm_kernel<false><<<gproj, 256>>>(h, CC, 0, wk, CC, 0, k, CC, 0, bk, nullptr, 1.f, Mtot, CC, CC);
    gemm_kernel<false><<<gproj, 256>>>(h, CC, 0, wv, CC, 0, v, CC, 0, bv, nullptr, 1.f, Mtot, CC, CC);

    // 3) scores = alpha * Q @ K^T  (batched over z)
    dim3 gsc(NTOK/BN, NTOK/BM, Bb);
    gemm_kernel<true><<<gsc, 256>>>(q, CC, sNC, k, CC, sNC, s, NTOK, sNN,
                                    nullptr, nullptr, inv_sqrt_c, NTOK, NTOK, CC);

    // 4) softmax over keys
    softmax_kernel<<<Bb*NTOK, 256>>>(s);

    // 5) attn @ V  (batched)
    dim3 gav(CC/BN, NTOK/BM, Bb);
    gemm_kernel<false><<<gav, 256>>>(s, NTOK, sNN, v, CC, sNC, ao, CC, sNC,
                                     nullptr, nullptr, 1.f, NTOK, CC, NTOK);

    // 6) output projection + bias + residual -> d_out
    gemm_kernel<false><<<gproj, 256>>>(ao, CC, 0, wo, CC, 0, out, CC, 0, bo, x, 1.f, Mtot, CC, CC);
}

// round 8
// speedup vs baseline: 2.4831x; 2.4803x over previous
#include <cuda_runtime.h>
#include <math.h>
#include <stdint.h>

#define Bb 8
#define CC 512
#define GG 32
#define CGc (CC/GG)          /* 16 */
#define NTOK 4096
#define EPSV 1e-5f

// ---------------- scratch (device globals; no runtime allocation) ----------------
__device__ float g_h [(size_t)Bb*NTOK*CC];
__device__ float g_q [(size_t)Bb*NTOK*CC];
__device__ float g_k [(size_t)Bb*NTOK*CC];
__device__ float g_kt[(size_t)Bb*NTOK*CC];
__device__ float g_v [(size_t)Bb*NTOK*CC];
__device__ float g_ao[(size_t)Bb*NTOK*CC];
__device__ float g_s [(size_t)Bb*NTOK*NTOK];   // 512 MB scores

// ---------------- GroupNorm ----------------
__global__ void gn_kernel(const float* __restrict__ x,
                          const float* __restrict__ sc,
                          const float* __restrict__ bi,
                          float* __restrict__ h) {
    int b = blockIdx.x / GG, g = blockIdx.x % GG;
    const float* xp = x + (size_t)b*NTOK*CC + g*CGc;
    float*       hp = h + (size_t)b*NTOK*CC + g*CGc;
    int tid = threadIdx.x;

    float s = 0.f, ss = 0.f;
    for (int i = tid; i < NTOK*CGc; i += 256) {
        int n = i >> 4, c = i & 15;
        float v = xp[(size_t)n*CC + c];
        s += v; ss += v*v;
    }
    __shared__ float r1[256], r2[256];
    r1[tid] = s; r2[tid] = ss; __syncthreads();
    for (int o = 128; o > 0; o >>= 1) {
        if (tid < o) { r1[tid] += r1[tid+o]; r2[tid] += r2[tid+o]; }
        __syncthreads();
    }
    const float invn = 1.f / (float)(NTOK*CGc);
    float mean = r1[0] * invn;
    float var  = r2[0] * invn - mean*mean;
    float inv  = rsqrtf(var + EPSV);

    for (int i = tid; i < NTOK*CGc; i += 256) {
        int n = i >> 4, c = i & 15;
        float v = xp[(size_t)n*CC + c];
        hp[(size_t)n*CC + c] = (v - mean) * inv * sc[g*CGc + c] + bi[g*CGc + c];
    }
}

// ---------------- batched transpose: [b][NTOK][CC] -> [b][CC][NTOK] ----------------
__global__ void transpose_kernel(const float* __restrict__ in, float* __restrict__ out) {
    __shared__ float t[32][33];
    int b = blockIdx.z;
    int n0 = blockIdx.x * 32, c0 = blockIdx.y * 32;
    const float* ip = in  + (size_t)b*NTOK*CC;
    float*       op = out + (size_t)b*NTOK*CC;
    int x = threadIdx.x, y = threadIdx.y;   // 32 x 8
    #pragma unroll
    for (int i = 0; i < 32; i += 8)
        t[y+i][x] = ip[(size_t)(n0+y+i)*CC + c0 + x];
    __syncthreads();
    #pragma unroll
    for (int i = 0; i < 32; i += 8)
        op[(size_t)(c0+y+i)*NTOK + n0 + x] = t[x][y+i];
}

// ---------------- tf32 tensor-core GEMM ----------------
// C[M,N] = alpha * A[M,K] @ B[K,N] (+ bias over N) (+ resid), all row-major.
#define BM 128
#define BN 128
#define BK 32
#define SA 36                 /* As row stride (floats) */
#define SB 132                /* Bs row stride (floats) */
#define ASZ (BM*SA)           /* 4608 floats per A buffer */
#define BSZ (BK*SB)           /* 4224 floats per B buffer */
#define SMEM_BYTES ((2*ASZ + 2*BSZ) * 4)   /* 70656 */

__device__ __forceinline__ unsigned cvt_tf32(float f) {
    unsigned u;
    asm("cvt.rna.tf32.f32 %0, %1;" : "=r"(u) : "f"(f));
    return u;
}

__global__ __launch_bounds__(256)
void mma_gemm(const float* __restrict__ A, int lda, long long strA,
              const float* __restrict__ B, int ldb, long long strB,
              float* __restrict__ C, int ldc, long long strC,
              const float* __restrict__ bias,
              const float* __restrict__ resid,
              float alpha, int K)
{
    extern __shared__ float smf[];
    float* As = smf;             // 2 x [128][SA]
    float* Bs = smf + 2*ASZ;     // 2 x [32][SB]

    const float* Ab = A + (size_t)blockIdx.z * strA;
    const float* Bg = B + (size_t)blockIdx.z * strB;
    float*       Cb = C + (size_t)blockIdx.z * strC;

    const int m0 = blockIdx.y * BM, n0 = blockIdx.x * BN;
    const int tid = threadIdx.x, lane = tid & 31, wid = tid >> 5;
    const int wm = (wid >> 1) * 32;   // warp row offset (0..96)
    const int wn = (wid & 1)  * 64;   // warp col offset (0,64)

    // cp.async mapping: A tile 128x32 = 256 thr x 4 chunks of 16B (8 chunks/row)
    const int arow = tid >> 3, akc = (tid & 7) * 4;
    // B tile 32x128 = 256 thr x 4 chunks (32 chunks/row)
    const int brow = tid >> 5, bnc = (tid & 31) * 4;

    const float* agp = Ab + (size_t)(m0 + arow) * lda + akc;
    const float* bgp = Bg + (size_t)brow * ldb + n0 + bnc;

    unsigned asp[4], bsp[4];
    #pragma unroll
    for (int t = 0; t < 4; t++) {
        asp[t] = (unsigned)__cvta_generic_to_shared(&As[(arow + t*32)*SA + akc]);
        bsp[t] = (unsigned)__cvta_generic_to_shared(&Bs[(brow + t*8)*SB + bnc]);
    }
    const unsigned ABUFB = ASZ * 4, BBUFB = BSZ * 4;

    float acc[2][8][4];
    #pragma unroll
    for (int i = 0; i < 2; i++)
        #pragma unroll
        for (int j = 0; j < 8; j++)
            #pragma unroll
            for (int q = 0; q < 4; q++) acc[i][j][q] = 0.f;

    // ldmatrix A-fragment addressing (16B rows: thread j=lane>>3 picks block)
    const int a_r = wm + ((lane >> 3) & 1) * 8 + (lane & 7);
    const int a_k = ((lane >> 4) & 1) * 4;
    // B-fragment scalar-LDS indices (conflict-free with SB=132)
    const int b_k = lane & 3;
    const int b_n = wn + (lane >> 2);

    const int KIT = K / BK;

    // prologue
    #pragma unroll
    for (int t = 0; t < 4; t++) {
        asm volatile("cp.async.cg.shared.global [%0], [%1], 16;\n"
                     :: "r"(asp[t]), "l"(agp + (size_t)t*32*lda) : "memory");
        asm volatile("cp.async.cg.shared.global [%0], [%1], 16;\n"
                     :: "r"(bsp[t]), "l"(bgp + (size_t)t*8*ldb) : "memory");
    }
    asm volatile("cp.async.commit_group;\n" ::: "memory");

    int buf = 0;
    for (int it = 0; it < KIT; ++it) {
        asm volatile("cp.async.wait_group 0;\n" ::: "memory");
        __syncthreads();

        if (it + 1 < KIT) {
            const float* ag = agp + (size_t)(it+1)*BK;
            const float* bg = bgp + (size_t)(it+1)*BK*ldb;
            unsigned ob = (unsigned)(buf ^ 1);
            #pragma unroll
            for (int t = 0; t < 4; t++) {
                asm volatile("cp.async.cg.shared.global [%0], [%1], 16;\n"
                             :: "r"(asp[t] + ob*ABUFB), "l"(ag + (size_t)t*32*lda) : "memory");
                asm volatile("cp.async.cg.shared.global [%0], [%1], 16;\n"
                             :: "r"(bsp[t] + ob*BBUFB), "l"(bg + (size_t)t*8*ldb) : "memory");
            }
            asm volatile("cp.async.commit_group;\n" ::: "memory");
        }

        const float* Abuf = As + buf*ASZ;
        const float* Bbuf = Bs + buf*BSZ;

        #pragma unroll
        for (int ks = 0; ks < 4; ks++) {
            unsigned a[2][4];
            #pragma unroll
            for (int mt = 0; mt < 2; mt++) {
                unsigned addr = (unsigned)__cvta_generic_to_shared(
                    Abuf + (a_r + mt*16)*SA + ks*8 + a_k);
                asm volatile("ldmatrix.sync.aligned.m8n8.x4.shared.b16 {%0,%1,%2,%3}, [%4];"
                    : "=r"(a[mt][0]), "=r"(a[mt][1]), "=r"(a[mt][2]), "=r"(a[mt][3])
                    : "r"(addr));
            }
            #pragma unroll
            for (int mt = 0; mt < 2; mt++)
                #pragma unroll
                for (int q = 0; q < 4; q++)
                    a[mt][q] = cvt_tf32(__uint_as_float(a[mt][q]));

            #pragma unroll
            for (int nt = 0; nt < 8; nt++) {
                float b0f = Bbuf[(ks*8 +     b_k)*SB + b_n + nt*8];
                float b1f = Bbuf[(ks*8 + 4 + b_k)*SB + b_n + nt*8];
                unsigned b0 = cvt_tf32(b0f), b1 = cvt_tf32(b1f);
                #pragma unroll
                for (int mt = 0; mt < 2; mt++) {
                    asm volatile(
                        "mma.sync.aligned.m16n8k8.row.col.f32.tf32.tf32.f32 "
                        "{%0,%1,%2,%3}, {%4,%5,%6,%7}, {%8,%9}, {%0,%1,%2,%3};"
                        : "+f"(acc[mt][nt][0]), "+f"(acc[mt][nt][1]),
                          "+f"(acc[mt][nt][2]), "+f"(acc[mt][nt][3])
                        : "r"(a[mt][0]), "r"(a[mt][1]), "r"(a[mt][2]), "r"(a[mt][3]),
                          "r"(b0), "r"(b1));
                }
            }
        }
        buf ^= 1;
    }

    // epilogue: c0/c1 at (r, c..c+1), c2/c3 at (r+8, c..c+1)
    const int c_r = lane >> 2, c_c = (lane & 3) * 2;
    #pragma unroll
    for (int mt = 0; mt < 2; mt++) {
        #pragma unroll
        for (int nt = 0; nt < 8; nt++) {
            int row0 = m0 + wm + mt*16 + c_r;
            int col  = n0 + wn + nt*8 + c_c;
            float2 v0, v1;
            v0.x = acc[mt][nt][0]*alpha; v0.y = acc[mt][nt][1]*alpha;
            v1.x = acc[mt][nt][2]*alpha; v1.y = acc[mt][nt][3]*alpha;
            if (bias) {
                float bx = bias[col], by = bias[col+1];
                v0.x += bx; v0.y += by; v1.x += bx; v1.y += by;
            }
            if (resid) {
                float2 r0 = *(const float2*)(resid + (size_t)row0*ldc + col);
                float2 r1 = *(const float2*)(resid + (size_t)(row0+8)*ldc + col);
                v0.x += r0.x; v0.y += r0.y; v1.x += r1.x; v1.y += r1.y;
            }
            *(float2*)(Cb + (size_t)row0*ldc + col)     = v0;
            *(float2*)(Cb + (size_t)(row0+8)*ldc + col) = v1;
        }
    }
}

// ---------------- row softmax ----------------
__global__ void softmax_kernel(float* __restrict__ s) {
    size_t row = blockIdx.x;
    float* p = s + row * (size_t)NTOK;
    int tid = threadIdx.x;

    float vals[16];
    float m = -3.4e38f;
    #pragma unroll
    for (int t = 0; t < 16; t++) {
        vals[t] = p[tid + t*256];
        m = fmaxf(m, vals[t]);
    }
    __shared__ float red[256];
    red[tid] = m; __syncthreads();
    for (int o = 128; o > 0; o >>= 1) {
        if (tid < o) red[tid] = fmaxf(red[tid], red[tid+o]);
        __syncthreads();
    }
    m = red[0]; __syncthreads();

    float sum = 0.f;
    #pragma unroll
    for (int t = 0; t < 16; t++) {
        vals[t] = __expf(vals[t] - m);
        sum += vals[t];
    }
    red[tid] = sum; __syncthreads();
    for (int o = 128; o > 0; o >>= 1) {
        if (tid < o) red[tid] += red[tid+o];
        __syncthreads();
    }
    float r = 1.f / red[0];
    #pragma unroll
    for (int t = 0; t < 16; t++) p[tid + t*256] = vals[t] * r;
}

// ---------------- launch ----------------
extern "C" void kernel_launch(void* const* d_in, const int* in_sizes, int n_in,
                              void* d_out, int out_size) {
    const float* x  = (const float*)d_in[0];
    const float* gs = (const float*)d_in[1];
    const float* gb = (const float*)d_in[2];
    const float* wq = (const float*)d_in[3];
    const float* bq = (const float*)d_in[4];
    const float* wk = (const float*)d_in[5];
    const float* bk = (const float*)d_in[6];
    const float* wv = (const float*)d_in[7];
    const float* bv = (const float*)d_in[8];
    const float* wo = (const float*)d_in[9];
    const float* bo = (const float*)d_in[10];
    float* out = (float*)d_out;

    float *h, *q, *k, *kt, *v, *ao, *s;
    cudaGetSymbolAddress((void**)&h,  g_h);
    cudaGetSymbolAddress((void**)&q,  g_q);
    cudaGetSymbolAddress((void**)&k,  g_k);
    cudaGetSymbolAddress((void**)&kt, g_kt);
    cudaGetSymbolAddress((void**)&v,  g_v);
    cudaGetSymbolAddress((void**)&ao, g_ao);
    cudaGetSymbolAddress((void**)&s,  g_s);

    cudaFuncSetAttribute(mma_gemm, cudaFuncAttributeMaxDynamicSharedMemorySize, SMEM_BYTES);

    const long long sNC = (long long)NTOK * CC;
    const long long sNN = (long long)NTOK * NTOK;
    const int Mtot = Bb * NTOK;                      // 32768
    const float inv_sqrt_c = 0.044194173824159216f;  // 512^-0.5

    // 1) GroupNorm
    gn_kernel<<<Bb*GG, 256>>>(x, gs, gb, h);

    // 2) Q, K, V projections
    dim3 gproj(CC/BN, Mtot/BM, 1);
    mma_gemm<<<gproj, 256, SMEM_BYTES>>>(h, CC, 0, wq, CC, 0, q, CC, 0, bq, nullptr, 1.f, CC);
    mma_gemm<<<gproj, 256, SMEM_BYTES>>>(h, CC, 0, wk, CC, 0, k, CC, 0, bk, nullptr, 1.f, CC);
    mma_gemm<<<gproj, 256, SMEM_BYTES>>>(h, CC, 0, wv, CC, 0, v, CC, 0, bv, nullptr, 1.f, CC);

    // 3) K -> K^T per batch ([b][NTOK][CC] -> [b][CC][NTOK])
    dim3 gtr(NTOK/32, CC/32, Bb);
    transpose_kernel<<<gtr, dim3(32,8)>>>(k, kt);

    // 4) scores = alpha * Q @ K^T (batched; B = kt is [CC][NTOK])
    dim3 gsc(NTOK/BN, NTOK/BM, Bb);
    mma_gemm<<<gsc, 256, SMEM_BYTES>>>(q, CC, sNC, kt, NTOK, sNC, s, NTOK, sNN,
                                       nullptr, nullptr, inv_sqrt_c, CC);

    // 5) softmax over keys
    softmax_kernel<<<Bb*NTOK, 256>>>(s);

    // 6) attn @ V (batched)
    dim3 gav(CC/BN, NTOK/BM, Bb);
    mma_gemm<<<gav, 256, SMEM_BYTES>>>(s, NTOK, sNN, v, CC, sNC, ao, CC, sNC,
                                       nullptr, nullptr, 1.f, NTOK);

    // 7) output projection + bias + residual -> d_out
    mma_gemm<<<gproj, 256, SMEM_BYTES>>>(ao, CC, 0, wo, CC, 0, out, CC, 0, bo, x, 1.f, CC);
}

// round 9
// speedup vs baseline: 3.2009x; 1.2891x over previous
#include <cuda_runtime.h>
#include <math.h>
#include <stdint.h>

#define Bb 8
#define CC 512
#define GG 32
#define CGc (CC/GG)          /* 16 */
#define NTOK 4096
#define EPSV 1e-5f

// ---------------- scratch (device globals; no runtime allocation) ----------------
__device__ float g_h [(size_t)Bb*NTOK*CC];
__device__ float g_q [(size_t)Bb*NTOK*CC];
__device__ float g_k [(size_t)Bb*NTOK*CC];
__device__ float g_vt[(size_t)Bb*NTOK*CC];     // V transposed per batch: [CC][NTOK]
__device__ float g_v [(size_t)Bb*NTOK*CC];
__device__ float g_ao[(size_t)Bb*NTOK*CC];
__device__ float g_s [(size_t)Bb*NTOK*NTOK];   // 512 MB scores
__device__ float g_wt[4*(size_t)CC*CC];        // transposed weights

// ---------------- GroupNorm ----------------
__global__ void gn_kernel(const float* __restrict__ x,
                          const float* __restrict__ sc,
                          const float* __restrict__ bi,
                          float* __restrict__ h) {
    int b = blockIdx.x / GG, g = blockIdx.x % GG;
    const float* xp = x + (size_t)b*NTOK*CC + g*CGc;
    float*       hp = h + (size_t)b*NTOK*CC + g*CGc;
    int tid = threadIdx.x;

    float s = 0.f, ss = 0.f;
    for (int i = tid; i < NTOK*CGc; i += 256) {
        int n = i >> 4, c = i & 15;
        float v = xp[(size_t)n*CC + c];
        s += v; ss += v*v;
    }
    __shared__ float r1[256], r2[256];
    r1[tid] = s; r2[tid] = ss; __syncthreads();
    for (int o = 128; o > 0; o >>= 1) {
        if (tid < o) { r1[tid] += r1[tid+o]; r2[tid] += r2[tid+o]; }
        __syncthreads();
    }
    const float invn = 1.f / (float)(NTOK*CGc);
    float mean = r1[0] * invn;
    float var  = r2[0] * invn - mean*mean;
    float inv  = rsqrtf(var + EPSV);

    for (int i = tid; i < NTOK*CGc; i += 256) {
        int n = i >> 4, c = i & 15;
        float v = xp[(size_t)n*CC + c];
        hp[(size_t)n*CC + c] = (v - mean) * inv * sc[g*CGc + c] + bi[g*CGc + c];
    }
}

// ---------------- generic batched transpose: in[R][Cc] -> out[Cc][R] ----------------
__global__ void transpose_kernel(const float* __restrict__ in, float* __restrict__ out,
                                 int R, int Cc, long long sIn, long long sOut) {
    __shared__ float t[32][33];
    int b = blockIdx.z;
    int r0 = blockIdx.x * 32, c0 = blockIdx.y * 32;
    const float* ip = in  + (size_t)b*sIn;
    float*       op = out + (size_t)b*sOut;
    int x = threadIdx.x, y = threadIdx.y;   // 32 x 8
    #pragma unroll
    for (int i = 0; i < 32; i += 8)
        t[y+i][x] = ip[(size_t)(r0+y+i)*Cc + c0 + x];
    __syncthreads();
    #pragma unroll
    for (int i = 0; i < 32; i += 8)
        op[(size_t)(c0+y+i)*R + r0 + x] = t[x][y+i];
}

// ---------------- tf32 tensor-core GEMM ----------------
// C[M,N] = alpha * A[M,K] @ B[K,N] (+ bias over N) (+ resid), where B is
// supplied TRANSPOSED: Bt is [N][K] row-major. Both operand fragments come
// from ldmatrix; no cvt (HMMA.tf32 truncates fp32 mantissa in hardware).
#define BM 128
#define BN 128
#define BK 32
#define ST 36                  /* smem row stride (floats) for both tiles */
#define TSZ (128*ST)           /* 4608 floats per tile buffer */
#define SMEM_BYTES (4*TSZ*4)   /* 73728: As x2, Bs x2 */

__global__ __launch_bounds__(256)
void mma_gemm(const float* __restrict__ A, int lda, long long strA,
              const float* __restrict__ Bt, int ldbt, long long strB,
              float* __restrict__ C, int ldc, long long strC,
              const float* __restrict__ bias,
              const float* __restrict__ resid,
              float alpha, int K)
{
    extern __shared__ float smf[];
    float* As = smf;             // 2 x [128][ST]  (rows = m, cols = k)
    float* Bs = smf + 2*TSZ;     // 2 x [128][ST]  (rows = n, cols = k)

    const float* Ab = A  + (size_t)blockIdx.z * strA;
    const float* Bg = Bt + (size_t)blockIdx.z * strB;
    float*       Cb = C  + (size_t)blockIdx.z * strC;

    const int m0 = blockIdx.y * BM, n0 = blockIdx.x * BN;
    const int tid = threadIdx.x, lane = tid & 31, wid = tid >> 5;
    const int wm = (wid >> 1) * 32;   // warp row offset (0..96)
    const int wn = (wid & 1)  * 64;   // warp col offset (0,64)

    // identical cp.async mapping for both 128x32 tiles:
    const int trow = tid >> 3, tkc = (tid & 7) * 4;

    const float* agp = Ab + (size_t)(m0 + trow) * lda  + tkc;
    const float* bgp = Bg + (size_t)(n0 + trow) * ldbt + tkc;

    unsigned asp[4], bsp[4];
    #pragma unroll
    for (int t = 0; t < 4; t++) {
        asp[t] = (unsigned)__cvta_generic_to_shared(&As[(trow + t*32)*ST + tkc]);
        bsp[t] = (unsigned)__cvta_generic_to_shared(&Bs[(trow + t*32)*ST + tkc]);
    }
    const unsigned BUFB = TSZ * 4;

    float acc[2][8][4];
    #pragma unroll
    for (int i = 0; i < 2; i++)
        #pragma unroll
        for (int j = 0; j < 8; j++)
            #pragma unroll
            for (int q = 0; q < 4; q++) acc[i][j][q] = 0.f;

    // A-fragment ldmatrix addressing: matrices (r0-7,k0-3),(r8-15,k0-3),(r0-7,k4-7),(r8-15,k4-7)
    const int a_r  = wm + ((lane >> 3) & 1) * 8 + (lane & 7);
    const int a_k4 = ((lane >> 4) & 1) * 4;
    // B-fragment: matrices (n0-7,k0-3),(n0-7,k4-7),(n8-15,k0-3),(n8-15,k4-7)
    const int b_r  = wn + ((lane >> 4) & 1) * 8 + (lane & 7);
    const int b_k4 = ((lane >> 3) & 1) * 4;

    const int KIT = K / BK;

    // prologue
    #pragma unroll
    for (int t = 0; t < 4; t++) {
        asm volatile("cp.async.cg.shared.global [%0], [%1], 16;\n"
                     :: "r"(asp[t]), "l"(agp + (size_t)t*32*lda) : "memory");
        asm volatile("cp.async.cg.shared.global [%0], [%1], 16;\n"
                     :: "r"(bsp[t]), "l"(bgp + (size_t)t*32*ldbt) : "memory");
    }
    asm volatile("cp.async.commit_group;\n" ::: "memory");

    int buf = 0;
    for (int it = 0; it < KIT; ++it) {
        asm volatile("cp.async.wait_group 0;\n" ::: "memory");
        __syncthreads();

        if (it + 1 < KIT) {
            const float* ag = agp + (size_t)(it+1)*BK;
            const float* bg = bgp + (size_t)(it+1)*BK;
            unsigned ob = (unsigned)(buf ^ 1);
            #pragma unroll
            for (int t = 0; t < 4; t++) {
                asm volatile("cp.async.cg.shared.global [%0], [%1], 16;\n"
                             :: "r"(asp[t] + ob*BUFB), "l"(ag + (size_t)t*32*lda) : "memory");
                asm volatile("cp.async.cg.shared.global [%0], [%1], 16;\n"
                             :: "r"(bsp[t] + ob*BUFB), "l"(bg + (size_t)t*32*ldbt) : "memory");
            }
            asm volatile("cp.async.commit_group;\n" ::: "memory");
        }

        const float* Abuf = As + buf*TSZ;
        const float* Bbuf = Bs + buf*TSZ;

        #pragma unroll
        for (int ks = 0; ks < 4; ks++) {
            unsigned a[2][4];
            #pragma unroll
            for (int mt = 0; mt < 2; mt++) {
                unsigned addr = (unsigned)__cvta_generic_to_shared(
                    Abuf + (a_r + mt*16)*ST + ks*8 + a_k4);
                asm volatile("ldmatrix.sync.aligned.m8n8.x4.shared.b16 {%0,%1,%2,%3}, [%4];"
                    : "=r"(a[mt][0]), "=r"(a[mt][1]), "=r"(a[mt][2]), "=r"(a[mt][3])
                    : "r"(addr));
            }
            unsigned bf[4][4];
            #pragma unroll
            for (int p = 0; p < 4; p++) {
                unsigned addr = (unsigned)__cvta_generic_to_shared(
                    Bbuf + (b_r + p*16)*ST + ks*8 + b_k4);
                asm volatile("ldmatrix.sync.aligned.m8n8.x4.shared.b16 {%0,%1,%2,%3}, [%4];"
                    : "=r"(bf[p][0]), "=r"(bf[p][1]), "=r"(bf[p][2]), "=r"(bf[p][3])
                    : "r"(addr));
            }
            #pragma unroll
            for (int nt = 0; nt < 8; nt++) {
                unsigned b0 = bf[nt >> 1][(nt & 1) * 2];
                unsigned b1 = bf[nt >> 1][(nt & 1) * 2 + 1];
                #pragma unroll
                for (int mt = 0; mt < 2; mt++) {
                    asm volatile(
                        "mma.sync.aligned.m16n8k8.row.col.f32.tf32.tf32.f32 "
                        "{%0,%1,%2,%3}, {%4,%5,%6,%7}, {%8,%9}, {%0,%1,%2,%3};"
                        : "+f"(acc[mt][nt][0]), "+f"(acc[mt][nt][1]),
                          "+f"(acc[mt][nt][2]), "+f"(acc[mt][nt][3])
                        : "r"(a[mt][0]), "r"(a[mt][1]), "r"(a[mt][2]), "r"(a[mt][3]),
                          "r"(b0), "r"(b1));
                }
            }
        }
        buf ^= 1;
    }

    // epilogue: c0/c1 at (r, c..c+1), c2/c3 at (r+8, c..c+1)
    const int c_r = lane >> 2, c_c = (lane & 3) * 2;
    #pragma unroll
    for (int mt = 0; mt < 2; mt++) {
        #pragma unroll
        for (int nt = 0; nt < 8; nt++) {
            int row0 = m0 + wm + mt*16 + c_r;
            int col  = n0 + wn + nt*8 + c_c;
            float2 v0, v1;
            v0.x = acc[mt][nt][0]*alpha; v0.y = acc[mt][nt][1]*alpha;
            v1.x = acc[mt][nt][2]*alpha; v1.y = acc[mt][nt][3]*alpha;
            if (bias) {
                float bx = bias[col], by = bias[col+1];
                v0.x += bx; v0.y += by; v1.x += bx; v1.y += by;
            }
            if (resid) {
                float2 r0 = *(const float2*)(resid + (size_t)row0*ldc + col);
                float2 r1 = *(const float2*)(resid + (size_t)(row0+8)*ldc + col);
                v0.x += r0.x; v0.y += r0.y; v1.x += r1.x; v1.y += r1.y;
            }
            *(float2*)(Cb + (size_t)row0*ldc + col)     = v0;
            *(float2*)(Cb + (size_t)(row0+8)*ldc + col) = v1;
        }
    }
}

// ---------------- row softmax ----------------
__global__ void softmax_kernel(float* __restrict__ s) {
    size_t row = blockIdx.x;
    float* p = s + row * (size_t)NTOK;
    int tid = threadIdx.x;

    float vals[16];
    float m = -3.4e38f;
    #pragma unroll
    for (int t = 0; t < 16; t++) {
        vals[t] = p[tid + t*256];
        m = fmaxf(m, vals[t]);
    }
    __shared__ float red[256];
    red[tid] = m; __syncthreads();
    for (int o = 128; o > 0; o >>= 1) {
        if (tid < o) red[tid] = fmaxf(red[tid], red[tid+o]);
        __syncthreads();
    }
    m = red[0]; __syncthreads();

    float sum = 0.f;
    #pragma unroll
    for (int t = 0; t < 16; t++) {
        vals[t] = __expf(vals[t] - m);
        sum += vals[t];
    }
    red[tid] = sum; __syncthreads();
    for (int o = 128; o > 0; o >>= 1) {
        if (tid < o) red[tid] += red[tid+o];
        __syncthreads();
    }
    float r = 1.f / red[0];
    #pragma unroll
    for (int t = 0; t < 16; t++) p[tid + t*256] = vals[t] * r;
}

// ---------------- launch ----------------
extern "C" void kernel_launch(void* const* d_in, const int* in_sizes, int n_in,
                              void* d_out, int out_size) {
    const float* x  = (const float*)d_in[0];
    const float* gs = (const float*)d_in[1];
    const float* gb = (const float*)d_in[2];
    const float* wq = (const float*)d_in[3];
    const float* bq = (const float*)d_in[4];
    const float* wk = (const float*)d_in[5];
    const float* bk = (const float*)d_in[6];
    const float* wv = (const float*)d_in[7];
    const float* bv = (const float*)d_in[8];
    const float* wo = (const float*)d_in[9];
    const float* bo = (const float*)d_in[10];
    float* out = (float*)d_out;

    float *h, *q, *k, *vt, *v, *ao, *s, *wt;
    cudaGetSymbolAddress((void**)&h,  g_h);
    cudaGetSymbolAddress((void**)&q,  g_q);
    cudaGetSymbolAddress((void**)&k,  g_k);
    cudaGetSymbolAddress((void**)&vt, g_vt);
    cudaGetSymbolAddress((void**)&v,  g_v);
    cudaGetSymbolAddress((void**)&ao, g_ao);
    cudaGetSymbolAddress((void**)&s,  g_s);
    cudaGetSymbolAddress((void**)&wt, g_wt);

    float* wqT = wt;
    float* wkT = wt + (size_t)CC*CC;
    float* wvT = wt + 2*(size_t)CC*CC;
    float* woT = wt + 3*(size_t)CC*CC;

    cudaFuncSetAttribute(mma_gemm, cudaFuncAttributeMaxDynamicSharedMemorySize, SMEM_BYTES);

    const long long sNC = (long long)NTOK * CC;
    const long long sNN = (long long)NTOK * NTOK;
    const int Mtot = Bb * NTOK;                      // 32768
    const float inv_sqrt_c = 0.044194173824159216f;  // 512^-0.5

    // 0) transpose weights [C][C] -> [C][C]^T (tiny)
    dim3 gtw(CC/32, CC/32, 1);
    dim3 tb(32, 8);
    transpose_kernel<<<gtw, tb>>>(wq, wqT, CC, CC, 0, 0);
    transpose_kernel<<<gtw, tb>>>(wk, wkT, CC, CC, 0, 0);
    transpose_kernel<<<gtw, tb>>>(wv, wvT, CC, CC, 0, 0);
    transpose_kernel<<<gtw, tb>>>(wo, woT, CC, CC, 0, 0);

    // 1) GroupNorm
    gn_kernel<<<Bb*GG, 256>>>(x, gs, gb, h);

    // 2) Q, K, V projections (Bt = W^T, ldbt = C)
    dim3 gproj(CC/BN, Mtot/BM, 1);
    mma_gemm<<<gproj, 256, SMEM_BYTES>>>(h, CC, 0, wqT, CC, 0, q, CC, 0, bq, nullptr, 1.f, CC);
    mma_gemm<<<gproj, 256, SMEM_BYTES>>>(h, CC, 0, wkT, CC, 0, k, CC, 0, bk, nullptr, 1.f, CC);
    mma_gemm<<<gproj, 256, SMEM_BYTES>>>(h, CC, 0, wvT, CC, 0, v, CC, 0, bv, nullptr, 1.f, CC);

    // 3) V -> V^T per batch ([NTOK][CC] -> [CC][NTOK])
    dim3 gtv(NTOK/32, CC/32, Bb);
    transpose_kernel<<<gtv, tb>>>(v, vt, NTOK, CC, sNC, sNC);

    // 4) scores = alpha * Q @ K^T : Bt = K as stored ([NTOK][CC], n-major over keys)
    dim3 gsc(NTOK/BN, NTOK/BM, Bb);
    mma_gemm<<<gsc, 256, SMEM_BYTES>>>(q, CC, sNC, k, CC, sNC, s, NTOK, sNN,
                                       nullptr, nullptr, inv_sqrt_c, CC);

    // 5) softmax over keys
    softmax_kernel<<<Bb*NTOK, 256>>>(s);

    // 6) attn @ V : Bt = V^T ([CC][NTOK]), K = NTOK
    dim3 gav(CC/BN, NTOK/BM, Bb);
    mma_gemm<<<gav, 256, SMEM_BYTES>>>(s, NTOK, sNN, vt, NTOK, sNC, ao, CC, sNC,
                                       nullptr, nullptr, 1.f, NTOK);

    // 7) output projection + bias + residual -> d_out
    mma_gemm<<<gproj, 256, SMEM_BYTES>>>(ao, CC, 0, woT, CC, 0, out, CC, 0, bo, x, 1.f, CC);
}

// round 11
// speedup vs baseline: 3.6620x; 1.1440x over previous
#include <cuda_runtime.h>
#include <cuda_fp16.h>
#include <math.h>
#include <stdint.h>

#define Bb 8
#define CC 512
#define GG 32
#define CGc 16
#define NTOK 4096
#define EPSV 1e-5f

// ---------------- scratch (device globals; no runtime allocation) ----------------
__device__ float  g_h [(size_t)Bb*NTOK*CC];
__device__ float  g_q [(size_t)Bb*NTOK*CC];
__device__ float  g_k [(size_t)Bb*NTOK*CC];
__device__ float  g_v [(size_t)Bb*NTOK*CC];
__device__ __half g_vth[(size_t)Bb*NTOK*CC];      // V^T per batch, fp16: [CC][NTOK]
__device__ float  g_ao[(size_t)Bb*NTOK*CC];
__device__ float  g_s [(size_t)Bb*NTOK*NTOK];     // fp32 scores (512 MB)
__device__ __half g_p [(size_t)Bb*NTOK*NTOK];     // fp16 probabilities (256 MB)
__device__ float  g_wt[4*(size_t)CC*CC];          // transposed weights

// ---------------- GroupNorm ----------------
__global__ void gn_kernel(const float* __restrict__ x,
                          const float* __restrict__ sc,
                          const float* __restrict__ bi,
                          float* __restrict__ h) {
    int b = blockIdx.x / GG, g = blockIdx.x % GG;
    const float* xp = x + (size_t)b*NTOK*CC + g*CGc;
    float*       hp = h + (size_t)b*NTOK*CC + g*CGc;
    int tid = threadIdx.x;

    float s = 0.f, ss = 0.f;
    for (int i = tid; i < NTOK*CGc; i += 256) {
        int n = i >> 4, c = i & 15;
        float v = xp[(size_t)n*CC + c];
        s += v; ss += v*v;
    }
    __shared__ float r1[256], r2[256];
    r1[tid] = s; r2[tid] = ss; __syncthreads();
    for (int o = 128; o > 0; o >>= 1) {
        if (tid < o) { r1[tid] += r1[tid+o]; r2[tid] += r2[tid+o]; }
        __syncthreads();
    }
    const float invn = 1.f / (float)(NTOK*CGc);
    float mean = r1[0] * invn;
    float var  = r2[0] * invn - mean*mean;
    float inv  = rsqrtf(var + EPSV);

    for (int i = tid; i < NTOK*CGc; i += 256) {
        int n = i >> 4, c = i & 15;
        float v = xp[(size_t)n*CC + c];
        hp[(size_t)n*CC + c] = (v - mean) * inv * sc[g*CGc + c] + bi[g*CGc + c];
    }
}

// ---------------- batched transpose fp32: in[R][Cc] -> out[Cc][R] ----------------
__global__ void transpose_kernel(const float* __restrict__ in, float* __restrict__ out,
                                 int R, int Cc, long long sIn, long long sOut) {
    __shared__ float t[32][33];
    int b = blockIdx.z;
    int r0 = blockIdx.x * 32, c0 = blockIdx.y * 32;
    const float* ip = in  + (size_t)b*sIn;
    float*       op = out + (size_t)b*sOut;
    int x = threadIdx.x, y = threadIdx.y;
    #pragma unroll
    for (int i = 0; i < 32; i += 8)
        t[y+i][x] = ip[(size_t)(r0+y+i)*Cc + c0 + x];
    __syncthreads();
    #pragma unroll
    for (int i = 0; i < 32; i += 8)
        op[(size_t)(c0+y+i)*R + r0 + x] = t[x][y+i];
}

// ---------------- batched transpose + fp32->fp16: in[R][Cc] -> out[Cc][R] ----------------
__global__ void transpose_h_kernel(const float* __restrict__ in, __half* __restrict__ out,
                                   int R, int Cc, long long sIn, long long sOut) {
    __shared__ float t[32][33];
    int b = blockIdx.z;
    int r0 = blockIdx.x * 32, c0 = blockIdx.y * 32;
    const float* ip = in  + (size_t)b*sIn;
    __half*      op = out + (size_t)b*sOut;
    int x = threadIdx.x, y = threadIdx.y;
    #pragma unroll
    for (int i = 0; i < 32; i += 8)
        t[y+i][x] = ip[(size_t)(r0+y+i)*Cc + c0 + x];
    __syncthreads();
    #pragma unroll
    for (int i = 0; i < 32; i += 8)
        op[(size_t)(c0+y+i)*R + r0 + x] = __float2half(t[x][y+i]);
}

// ---------------- tf32 tensor-core GEMM (unchanged from R9, passing) ----------------
// C[M,N] = alpha * A[M,K] @ Bt^T (+bias)(+resid); Bt is [N][K] row-major.
#define BM 128
#define BN 128
#define BK 32
#define ST 36
#define TSZ (128*ST)
#define SMEM_BYTES (4*TSZ*4)

__global__ __launch_bounds__(256)
void mma_gemm(const float* __restrict__ A, int lda, long long strA,
              const float* __restrict__ Bt, int ldbt, long long strB,
              float* __restrict__ C, int ldc, long long strC,
              const float* __restrict__ bias,
              const float* __restrict__ resid,
              float alpha, int K)
{
    extern __shared__ float smf[];
    float* As = smf;
    float* Bs = smf + 2*TSZ;

    const float* Ab = A  + (size_t)blockIdx.z * strA;
    const float* Bg = Bt + (size_t)blockIdx.z * strB;
    float*       Cb = C  + (size_t)blockIdx.z * strC;

    const int m0 = blockIdx.y * BM, n0 = blockIdx.x * BN;
    const int tid = threadIdx.x, lane = tid & 31, wid = tid >> 5;
    const int wm = (wid >> 1) * 32;
    const int wn = (wid & 1)  * 64;

    const int trow = tid >> 3, tkc = (tid & 7) * 4;

    const float* agp = Ab + (size_t)(m0 + trow) * lda  + tkc;
    const float* bgp = Bg + (size_t)(n0 + trow) * ldbt + tkc;

    unsigned asp[4], bsp[4];
    #pragma unroll
    for (int t = 0; t < 4; t++) {
        asp[t] = (unsigned)__cvta_generic_to_shared(&As[(trow + t*32)*ST + tkc]);
        bsp[t] = (unsigned)__cvta_generic_to_shared(&Bs[(trow + t*32)*ST + tkc]);
    }
    const unsigned BUFB = TSZ * 4;

    float acc[2][8][4];
    #pragma unroll
    for (int i = 0; i < 2; i++)
        #pragma unroll
        for (int j = 0; j < 8; j++)
            #pragma unroll
            for (int q = 0; q < 4; q++) acc[i][j][q] = 0.f;

    const int a_r  = wm + ((lane >> 3) & 1) * 8 + (lane & 7);
    const int a_k4 = ((lane >> 4) & 1) * 4;
    const int b_r  = wn + ((lane >> 4) & 1) * 8 + (lane & 7);
    const int b_k4 = ((lane >> 3) & 1) * 4;

    const int KIT = K / BK;

    #pragma unroll
    for (int t = 0; t < 4; t++) {
        asm volatile("cp.async.cg.shared.global [%0], [%1], 16;\n"
                     :: "r"(asp[t]), "l"(agp + (size_t)t*32*lda) : "memory");
        asm volatile("cp.async.cg.shared.global [%0], [%1], 16;\n"
                     :: "r"(bsp[t]), "l"(bgp + (size_t)t*32*ldbt) : "memory");
    }
    asm volatile("cp.async.commit_group;\n" ::: "memory");

    int buf = 0;
    for (int it = 0; it < KIT; ++it) {
        asm volatile("cp.async.wait_group 0;\n" ::: "memory");
        __syncthreads();

        if (it + 1 < KIT) {
            const float* ag = agp + (size_t)(it+1)*BK;
            const float* bg = bgp + (size_t)(it+1)*BK;
            unsigned ob = (unsigned)(buf ^ 1);
            #pragma unroll
            for (int t = 0; t < 4; t++) {
                asm volatile("cp.async.cg.shared.global [%0], [%1], 16;\n"
                             :: "r"(asp[t] + ob*BUFB), "l"(ag + (size_t)t*32*lda) : "memory");
                asm volatile("cp.async.cg.shared.global [%0], [%1], 16;\n"
                             :: "r"(bsp[t] + ob*BUFB), "l"(bg + (size_t)t*32*ldbt) : "memory");
            }
            asm volatile("cp.async.commit_group;\n" ::: "memory");
        }

        const float* Abuf = As + buf*TSZ;
        const float* Bbuf = Bs + buf*TSZ;

        #pragma unroll
        for (int ks = 0; ks < 4; ks++) {
            unsigned a[2][4];
            #pragma unroll
            for (int mt = 0; mt < 2; mt++) {
                unsigned addr = (unsigned)__cvta_generic_to_shared(
                    Abuf + (a_r + mt*16)*ST + ks*8 + a_k4);
                asm volatile("ldmatrix.sync.aligned.m8n8.x4.shared.b16 {%0,%1,%2,%3}, [%4];"
                    : "=r"(a[mt][0]), "=r"(a[mt][1]), "=r"(a[mt][2]), "=r"(a[mt][3])
                    : "r"(addr));
            }
            unsigned bf[4][4];
            #pragma unroll
            for (int p = 0; p < 4; p++) {
                unsigned addr = (unsigned)__cvta_generic_to_shared(
                    Bbuf + (b_r + p*16)*ST + ks*8 + b_k4);
                asm volatile("ldmatrix.sync.aligned.m8n8.x4.shared.b16 {%0,%1,%2,%3}, [%4];"
                    : "=r"(bf[p][0]), "=r"(bf[p][1]), "=r"(bf[p][2]), "=r"(bf[p][3])
                    : "r"(addr));
            }
            #pragma unroll
            for (int nt = 0; nt < 8; nt++) {
                unsigned b0 = bf[nt >> 1][(nt & 1) * 2];
                unsigned b1 = bf[nt >> 1][(nt & 1) * 2 + 1];
                #pragma unroll
                for (int mt = 0; mt < 2; mt++) {
                    asm volatile(
                        "mma.sync.aligned.m16n8k8.row.col.f32.tf32.tf32.f32 "
                        "{%0,%1,%2,%3}, {%4,%5,%6,%7}, {%8,%9}, {%0,%1,%2,%3};"
                        : "+f"(acc[mt][nt][0]), "+f"(acc[mt][nt][1]),
                          "+f"(acc[mt][nt][2]), "+f"(acc[mt][nt][3])
                        : "r"(a[mt][0]), "r"(a[mt][1]), "r"(a[mt][2]), "r"(a[mt][3]),
                          "r"(b0), "r"(b1));
                }
            }
        }
        buf ^= 1;
    }

    const int c_r = lane >> 2, c_c = (lane & 3) * 2;
    #pragma unroll
    for (int mt = 0; mt < 2; mt++) {
        #pragma unroll
        for (int nt = 0; nt < 8; nt++) {
            int row0 = m0 + wm + mt*16 + c_r;
            int col  = n0 + wn + nt*8 + c_c;
            float2 v0, v1;
            v0.x = acc[mt][nt][0]*alpha; v0.y = acc[mt][nt][1]*alpha;
            v1.x = acc[mt][nt][2]*alpha; v1.y = acc[mt][nt][3]*alpha;
            if (bias) {
                float bx = bias[col], by = bias[col+1];
                v0.x += bx; v0.y += by; v1.x += bx; v1.y += by;
            }
            if (resid) {
                float2 r0 = *(const float2*)(resid + (size_t)row0*ldc + col);
                float2 r1 = *(const float2*)(resid + (size_t)(row0+8)*ldc + col);
                v0.x += r0.x; v0.y += r0.y; v1.x += r1.x; v1.y += r1.y;
            }
            *(float2*)(Cb + (size_t)row0*ldc + col)     = v0;
            *(float2*)(Cb + (size_t)(row0+8)*ldc + col) = v1;
        }
    }
}

// ---------------- fp16 tensor-core GEMM (m16n8k16) ----------------
// C[M,N] = A[M,K] @ Bt^T ; A, Bt fp16 ([M][K] and [N][K] row-major), C fp32.
// 128x128 CTA tile, BK=32 halves, padded smem rows (40 halves = 80B, 16B-bank
// conflict-free: bank16 = (5r + c) mod 8 distinct over any 8 rows).
#define HST 40
#define HTSZ (128*HST)   /* halves per tile buffer */

__global__ __launch_bounds__(256)
void hgemm(const __half* __restrict__ A, int lda, long long strA,
           const __half* __restrict__ Bt, int ldbt, long long strB,
           float* __restrict__ C, int ldc, long long strC, int K)
{
    __shared__ __half As[2*HTSZ];
    __shared__ __half Bs[2*HTSZ];

    const __half* Ab = A  + (size_t)blockIdx.z * strA;
    const __half* Bg = Bt + (size_t)blockIdx.z * strB;
    float*        Cb = C  + (size_t)blockIdx.z * strC;

    const int m0 = blockIdx.y * 128, n0 = blockIdx.x * 128;
    const int tid = threadIdx.x, lane = tid & 31, wid = tid >> 5;
    const int wm = (wid >> 1) * 32;
    const int wn = (wid & 1)  * 64;

    // loads: 128 rows x 4 chunks(16B=8 halves); thread -> row=tid>>1, 2 chunks
    const int trow = tid >> 1, tch = (tid & 1) * 2;

    const __half* agp = Ab + (size_t)(m0 + trow) * lda  + tch*8;
    const __half* bgp = Bg + (size_t)(n0 + trow) * ldbt + tch*8;

    unsigned asp[2], bsp[2];
    #pragma unroll
    for (int c = 0; c < 2; c++) {
        asp[c] = (unsigned)__cvta_generic_to_shared(&As[trow*HST + (tch+c)*8]);
        bsp[c] = (unsigned)__cvta_generic_to_shared(&Bs[trow*HST + (tch+c)*8]);
    }
    const unsigned BUFB = HTSZ * 2;   // bytes per buffer

    float acc[2][8][4];
    #pragma unroll
    for (int i = 0; i < 2; i++)
        #pragma unroll
        for (int j = 0; j < 8; j++)
            #pragma unroll
            for (int q = 0; q < 4; q++) acc[i][j][q] = 0.f;

    // ldmatrix addressing (b16): lanes 0-7 m0-rows, 8-15 m1(+8 rows),
    // 16-23 m2(k+8), 24-31 m3(+8 rows, k+8)
    const int f_r  = (lane & 7) + ((lane >> 3) & 1) * 8;
    const int f_kh = ((lane >> 4) & 1) * 8;

    const int KIT = K / 32;

    #pragma unroll
    for (int c = 0; c < 2; c++) {
        asm volatile("cp.async.cg.shared.global [%0], [%1], 16;\n"
                     :: "r"(asp[c]), "l"(agp + c*8) : "memory");
        asm volatile("cp.async.cg.shared.global [%0], [%1], 16;\n"
                     :: "r"(bsp[c]), "l"(bgp + c*8) : "memory");
    }
    asm volatile("cp.async.commit_group;\n" ::: "memory");

    int buf = 0;
    for (int it = 0; it < KIT; ++it) {
        asm volatile("cp.async.wait_group 0;\n" ::: "memory");
        __syncthreads();

        if (it + 1 < KIT) {
            const __half* ag = agp + (size_t)(it+1)*32;
            const __half* bg = bgp + (size_t)(it+1)*32;
            unsigned ob = (unsigned)(buf ^ 1);
            #pragma unroll
            for (int c = 0; c < 2; c++) {
                asm volatile("cp.async.cg.shared.global [%0], [%1], 16;\n"
                             :: "r"(asp[c] + ob*BUFB), "l"(ag + c*8) : "memory");
                asm volatile("cp.async.cg.shared.global [%0], [%1], 16;\n"
                             :: "r"(bsp[c] + ob*BUFB), "l"(bg + c*8) : "memory");
            }
            asm volatile("cp.async.commit_group;\n" ::: "memory");
        }

        const __half* Abuf = As + buf*HTSZ;
        const __half* Bbuf = Bs + buf*HTSZ;

        #pragma unroll
        for (int ks = 0; ks < 2; ks++) {         // two k16 steps per 32-chunk
            unsigned a[2][4];
            #pragma unroll
            for (int mt = 0; mt < 2; mt++) {
                unsigned addr = (unsigned)__cvta_generic_to_shared(
                    Abuf + (wm + mt*16 + f_r)*HST + ks*16 + f_kh);
                asm volatile("ldmatrix.sync.aligned.m8n8.x4.shared.b16 {%0,%1,%2,%3}, [%4];"
                    : "=r"(a[mt][0]), "=r"(a[mt][1]), "=r"(a[mt][2]), "=r"(a[mt][3])
                    : "r"(addr));
            }
            unsigned bf[4][4];
            #pragma unroll
            for (int p = 0; p < 4; p++) {
                unsigned addr = (unsigned)__cvta_generic_to_shared(
                    Bbuf + (wn + p*16 + f_r)*HST + ks*16 + f_kh);
                asm volatile("ldmatrix.sync.aligned.m8n8.x4.shared.b16 {%0,%1,%2,%3}, [%4];"
                    : "=r"(bf[p][0]), "=r"(bf[p][1]), "=r"(bf[p][2]), "=r"(bf[p][3])
                    : "r"(addr));
            }
            // n8-tile nt: fragment regs = matrices {nt&1 ? (1,3) : (0,2)} of pack nt>>1
            #pragma unroll
            for (int nt = 0; nt < 8; nt++) {
                unsigned b0 = bf[nt >> 1][(nt & 1)];
                unsigned b1 = bf[nt >> 1][(nt & 1) + 2];
                #pragma unroll
                for (int mt = 0; mt < 2; mt++) {
                    asm volatile(
                        "mma.sync.aligned.m16n8k16.row.col.f32.f16.f16.f32 "
                        "{%0,%1,%2,%3}, {%4,%5,%6,%7}, {%8,%9}, {%0,%1,%2,%3};"
                        : "+f"(acc[mt][nt][0]), "+f"(acc[mt][nt][1]),
                          "+f"(acc[mt][nt][2]), "+f"(acc[mt][nt][3])
                        : "r"(a[mt][0]), "r"(a[mt][1]), "r"(a[mt][2]), "r"(a[mt][3]),
                          "r"(b0), "r"(b1));
                }
            }
        }
        buf ^= 1;
    }

    const int c_r = lane >> 2, c_c = (lane & 3) * 2;
    #pragma unroll
    for (int mt = 0; mt < 2; mt++) {
        #pragma unroll
        for (int nt = 0; nt < 8; nt++) {
            int row0 = m0 + wm + mt*16 + c_r;
            int col  = n0 + wn + nt*8 + c_c;
            *(float2*)(Cb + (size_t)row0*ldc + col) =
                make_float2(acc[mt][nt][0], acc[mt][nt][1]);
            *(float2*)(Cb + (size_t)(row0+8)*ldc + col) =
                make_float2(acc[mt][nt][2], acc[mt][nt][3]);
        }
    }
}

// ---------------- row softmax: fp32 in -> fp16 out ----------------
__global__ void softmax_kernel(const float* __restrict__ s, __half* __restrict__ pout) {
    const float4* p = reinterpret_cast<const float4*>(s) + (size_t)blockIdx.x * (NTOK/4);
    __half2* po = reinterpret_cast<__half2*>(pout + (size_t)blockIdx.x * NTOK);
    int tid = threadIdx.x;

    float4 v[4];
    float m = -3.4e38f;
    #pragma unroll
    for (int t = 0; t < 4; t++) {
        v[t] = p[tid + t*256];
        m = fmaxf(m, fmaxf(fmaxf(v[t].x, v[t].y), fmaxf(v[t].z, v[t].w)));
    }
    __shared__ float red[256];
    red[tid] = m; __syncthreads();
    for (int o = 128; o > 0; o >>= 1) {
        if (tid < o) red[tid] = fmaxf(red[tid], red[tid+o]);
        __syncthreads();
    }
    m = red[0]; __syncthreads();

    float sum = 0.f;
    #pragma unroll
    for (int t = 0; t < 4; t++) {
        v[t].x = __expf(v[t].x - m); v[t].y = __expf(v[t].y - m);
        v[t].z = __expf(v[t].z - m); v[t].w = __expf(v[t].w - m);
        sum += v[t].x + v[t].y + v[t].z + v[t].w;
    }
    red[tid] = sum; __syncthreads();
    for (int o = 128; o > 0; o >>= 1) {
        if (tid < o) red[tid] += red[tid+o];
        __syncthreads();
    }
    float r = 1.f / red[0];
    #pragma unroll
    for (int t = 0; t < 4; t++) {
        int idx = tid + t*256;
        po[idx*2]   = __floats2half2_rn(v[t].x * r, v[t].y * r);
        po[idx*2+1] = __floats2half2_rn(v[t].z * r, v[t].w * r);
    }
}

// ---------------- launch ----------------
extern "C" void kernel_launch(void* const* d_in, const int* in_sizes, int n_in,
                              void* d_out, int out_size) {
    const float* x  = (const float*)d_in[0];
    const float* gs = (const float*)d_in[1];
    const float* gb = (const float*)d_in[2];
    const float* wq = (const float*)d_in[3];
    const float* bq = (const float*)d_in[4];
    const float* wk = (const float*)d_in[5];
    const float* bk = (const float*)d_in[6];
    const float* wv = (const float*)d_in[7];
    const float* bv = (const float*)d_in[8];
    const float* wo = (const float*)d_in[9];
    const float* bo = (const float*)d_in[10];
    float* out = (float*)d_out;

    float *h, *q, *k, *v, *ao, *s, *wt;
    __half *vth, *pp;
    cudaGetSymbolAddress((void**)&h,   g_h);
    cudaGetSymbolAddress((void**)&q,   g_q);
    cudaGetSymbolAddress((void**)&k,   g_k);
    cudaGetSymbolAddress((void**)&v,   g_v);
    cudaGetSymbolAddress((void**)&vth, g_vth);
    cudaGetSymbolAddress((void**)&ao,  g_ao);
    cudaGetSymbolAddress((void**)&s,   g_s);
    cudaGetSymbolAddress((void**)&pp,  g_p);
    cudaGetSymbolAddress((void**)&wt,  g_wt);

    float* wqT = wt;
    float* wkT = wt +   (size_t)CC*CC;
    float* wvT = wt + 2*(size_t)CC*CC;
    float* woT = wt + 3*(size_t)CC*CC;

    cudaFuncSetAttribute(mma_gemm, cudaFuncAttributeMaxDynamicSharedMemorySize, SMEM_BYTES);

    const long long sNC = (long long)NTOK * CC;
    const long long sNN = (long long)NTOK * NTOK;
    const int Mtot = Bb * NTOK;                      // 32768
    const float inv_sqrt_c = 0.044194173824159216f;  // 512^-0.5

    // 0) weight transposes (tiny)
    dim3 gtw(CC/32, CC/32, 1);
    dim3 tb(32, 8);
    transpose_kernel<<<gtw, tb>>>(wq, wqT, CC, CC, 0, 0);
    transpose_kernel<<<gtw, tb>>>(wk, wkT, CC, CC, 0, 0);
    transpose_kernel<<<gtw, tb>>>(wv, wvT, CC, CC, 0, 0);
    transpose_kernel<<<gtw, tb>>>(wo, woT, CC, CC, 0, 0);

    // 1) GroupNorm
    gn_kernel<<<Bb*GG, 256>>>(x, gs, gb, h);

    // 2) Q, K, V projections (tf32)
    dim3 gproj(CC/BN, Mtot/BM, 1);
    mma_gemm<<<gproj, 256, SMEM_BYTES>>>(h, CC, 0, wqT, CC, 0, q, CC, 0, bq, nullptr, 1.f, CC);
    mma_gemm<<<gproj, 256, SMEM_BYTES>>>(h, CC, 0, wkT, CC, 0, k, CC, 0, bk, nullptr, 1.f, CC);
    mma_gemm<<<gproj, 256, SMEM_BYTES>>>(h, CC, 0, wvT, CC, 0, v, CC, 0, bv, nullptr, 1.f, CC);

    // 3) V -> V^T fp16 per batch ([NTOK][CC] f32 -> [CC][NTOK] f16)
    dim3 gtv(NTOK/32, CC/32, Bb);
    transpose_h_kernel<<<gtv, tb>>>(v, vth, NTOK, CC, sNC, sNC);

    // 4) scores = alpha * Q @ K^T (tf32; Bt = K as stored)
    dim3 gsc(NTOK/BN, NTOK/BM, Bb);
    mma_gemm<<<gsc, 256, SMEM_BYTES>>>(q, CC, sNC, k, CC, sNC, s, NTOK, sNN,
                                       nullptr, nullptr, inv_sqrt_c, CC);

    // 5) softmax: fp32 scores -> fp16 P
    softmax_kernel<<<Bb*NTOK, 256>>>(s, pp);

    // 6) attn @ V in fp16 (Bt = V^T fp16, K = NTOK)
    dim3 gav(CC/128, NTOK/128, Bb);
    hgemm<<<gav, 256>>>(pp, NTOK, sNN, vth, NTOK, sNC, ao, CC, sNC, NTOK);

    // 7) output projection + bias + residual -> d_out (tf32)
    mma_gemm<<<gproj, 256, SMEM_BYTES>>>(ao, CC, 0, woT, CC, 0, out, CC, 0, bo, x, 1.f, CC);
}

// round 12
// speedup vs baseline: 4.2963x; 1.1732x over previous
#include <cuda_runtime.h>
#include <cuda_fp16.h>
#include <math.h>
#include <stdint.h>

#define Bb 8
#define CC 512
#define GG 32
#define CGc 16
#define NTOK 4096
#define EPSV 1e-5f

// ---------------- scratch (device globals; no runtime allocation) ----------------
__device__ __half g_h  [(size_t)Bb*NTOK*CC];          // GN output, fp16
__device__ __half g_qkv[(size_t)Bb*NTOK*3*CC];        // packed q|k|v, fp16
__device__ __half g_vth[(size_t)Bb*NTOK*CC];          // V^T per batch fp16 [CC][NTOK]
__device__ __half g_ao [(size_t)Bb*NTOK*CC];          // attention output fp16
__device__ float  g_s  [(size_t)Bb*NTOK*NTOK];        // fp32 scores
__device__ __half g_p  [(size_t)Bb*NTOK*NTOK];        // fp16 probabilities
__device__ __half g_w16[4*(size_t)CC*CC];             // wqkvT (3 sections) + woT, fp16
__device__ float  g_bqkv[3*CC];                       // packed biases

// ---------------- GroupNorm -> fp16 ----------------
__global__ void gn_kernel(const float* __restrict__ x,
                          const float* __restrict__ sc,
                          const float* __restrict__ bi,
                          __half* __restrict__ h) {
    int b = blockIdx.x / GG, g = blockIdx.x % GG;
    const float* xp = x + (size_t)b*NTOK*CC + g*CGc;
    __half*      hp = h + (size_t)b*NTOK*CC + g*CGc;
    int tid = threadIdx.x;

    float s = 0.f, ss = 0.f;
    for (int i = tid; i < NTOK*CGc; i += 256) {
        int n = i >> 4, c = i & 15;
        float v = xp[(size_t)n*CC + c];
        s += v; ss += v*v;
    }
    __shared__ float r1[256], r2[256];
    r1[tid] = s; r2[tid] = ss; __syncthreads();
    for (int o = 128; o > 0; o >>= 1) {
        if (tid < o) { r1[tid] += r1[tid+o]; r2[tid] += r2[tid+o]; }
        __syncthreads();
    }
    const float invn = 1.f / (float)(NTOK*CGc);
    float mean = r1[0] * invn;
    float var  = r2[0] * invn - mean*mean;
    float inv  = rsqrtf(var + EPSV);

    for (int i = tid; i < NTOK*CGc; i += 256) {
        int n = i >> 4, c = i & 15;
        float v = xp[(size_t)n*CC + c];
        hp[(size_t)n*CC + c] =
            __float2half((v - mean) * inv * sc[g*CGc + c] + bi[g*CGc + c]);
    }
}

// ---------------- transpose fp32 -> fp16: in[R][Cc] -> out[Cc][R] ----------------
__global__ void transpose_f2h(const float* __restrict__ in, __half* __restrict__ out,
                              int R, int Cc) {
    __shared__ float t[32][33];
    int r0 = blockIdx.x * 32, c0 = blockIdx.y * 32;
    int x = threadIdx.x, y = threadIdx.y;
    #pragma unroll
    for (int i = 0; i < 32; i += 8)
        t[y+i][x] = in[(size_t)(r0+y+i)*Cc + c0 + x];
    __syncthreads();
    #pragma unroll
    for (int i = 0; i < 32; i += 8)
        out[(size_t)(c0+y+i)*R + r0 + x] = __float2half(t[x][y+i]);
}

// ---------------- batched transpose fp16: in[R][ldi] -> out[Cc][R] ----------------
__global__ void transpose_h2h(const __half* __restrict__ in, __half* __restrict__ out,
                              int R, int Cc, int ldi,
                              long long sIn, long long sOut) {
    __shared__ __half t[32][34];
    int b = blockIdx.z;
    int r0 = blockIdx.x * 32, c0 = blockIdx.y * 32;
    const __half* ip = in  + (size_t)b*sIn;
    __half*       op = out + (size_t)b*sOut;
    int x = threadIdx.x, y = threadIdx.y;
    #pragma unroll
    for (int i = 0; i < 32; i += 8)
        t[y+i][x] = ip[(size_t)(r0+y+i)*ldi + c0 + x];
    __syncthreads();
    #pragma unroll
    for (int i = 0; i < 32; i += 8)
        op[(size_t)(c0+y+i)*R + r0 + x] = t[x][y+i];
}

// ---------------- bias pack ----------------
__global__ void pack_bias(const float* __restrict__ bq, const float* __restrict__ bk,
                          const float* __restrict__ bv, float* __restrict__ o) {
    int i = threadIdx.x + blockIdx.x * 256;
    if (i < CC)            o[i] = bq[i];
    else if (i < 2*CC)     o[i] = bk[i - CC];
    else if (i < 3*CC)     o[i] = bv[i - 2*CC];
}

// ---------------- fp16 tensor-core GEMM (m16n8k16) ----------------
// C[M,N] = alpha * A[M,K] @ Bt^T (+bias)(+resid); A [M][K] fp16 (lda), Bt [N][K]
// fp16 (ldbt). HOUT: C fp16, else fp32. resid only in fp32 path.
#define HST 40
#define HTSZ (128*HST)

template<bool HOUT>
__global__ __launch_bounds__(256)
void hgemm(const __half* __restrict__ A, int lda, long long strA,
           const __half* __restrict__ Bt, int ldbt, long long strB,
           void* __restrict__ Cv, int ldc, long long strC,
           const float* __restrict__ bias,
           const float* __restrict__ resid,
           float alpha, int K)
{
    __shared__ __half As[2*HTSZ];
    __shared__ __half Bs[2*HTSZ];

    const __half* Ab = A  + (size_t)blockIdx.z * strA;
    const __half* Bg = Bt + (size_t)blockIdx.z * strB;

    const int m0 = blockIdx.y * 128, n0 = blockIdx.x * 128;
    const int tid = threadIdx.x, lane = tid & 31, wid = tid >> 5;
    const int wm = (wid >> 1) * 32;
    const int wn = (wid & 1)  * 64;

    const int trow = tid >> 1, tch = (tid & 1) * 2;

    const __half* agp = Ab + (size_t)(m0 + trow) * lda  + tch*8;
    const __half* bgp = Bg + (size_t)(n0 + trow) * ldbt + tch*8;

    unsigned asp[2], bsp[2];
    #pragma unroll
    for (int c = 0; c < 2; c++) {
        asp[c] = (unsigned)__cvta_generic_to_shared(&As[trow*HST + (tch+c)*8]);
        bsp[c] = (unsigned)__cvta_generic_to_shared(&Bs[trow*HST + (tch+c)*8]);
    }
    const unsigned BUFB = HTSZ * 2;

    float acc[2][8][4];
    #pragma unroll
    for (int i = 0; i < 2; i++)
        #pragma unroll
        for (int j = 0; j < 8; j++)
            #pragma unroll
            for (int q = 0; q < 4; q++) acc[i][j][q] = 0.f;

    const int f_r  = (lane & 7) + ((lane >> 3) & 1) * 8;
    const int f_kh = ((lane >> 4) & 1) * 8;

    const int KIT = K / 32;

    #pragma unroll
    for (int c = 0; c < 2; c++) {
        asm volatile("cp.async.cg.shared.global [%0], [%1], 16;\n"
                     :: "r"(asp[c]), "l"(agp + c*8) : "memory");
        asm volatile("cp.async.cg.shared.global [%0], [%1], 16;\n"
                     :: "r"(bsp[c]), "l"(bgp + c*8) : "memory");
    }
    asm volatile("cp.async.commit_group;\n" ::: "memory");

    int buf = 0;
    for (int it = 0; it < KIT; ++it) {
        asm volatile("cp.async.wait_group 0;\n" ::: "memory");
        __syncthreads();

        if (it + 1 < KIT) {
            const __half* ag = agp + (size_t)(it+1)*32;
            const __half* bg = bgp + (size_t)(it+1)*32;
            unsigned ob = (unsigned)(buf ^ 1);
            #pragma unroll
            for (int c = 0; c < 2; c++) {
                asm volatile("cp.async.cg.shared.global [%0], [%1], 16;\n"
                             :: "r"(asp[c] + ob*BUFB), "l"(ag + c*8) : "memory");
                asm volatile("cp.async.cg.shared.global [%0], [%1], 16;\n"
                             :: "r"(bsp[c] + ob*BUFB), "l"(bg + c*8) : "memory");
            }
            asm volatile("cp.async.commit_group;\n" ::: "memory");
        }

        const __half* Abuf = As + buf*HTSZ;
        const __half* Bbuf = Bs + buf*HTSZ;

        #pragma unroll
        for (int ks = 0; ks < 2; ks++) {
            unsigned a[2][4];
            #pragma unroll
            for (int mt = 0; mt < 2; mt++) {
                unsigned addr = (unsigned)__cvta_generic_to_shared(
                    Abuf + (wm + mt*16 + f_r)*HST + ks*16 + f_kh);
                asm volatile("ldmatrix.sync.aligned.m8n8.x4.shared.b16 {%0,%1,%2,%3}, [%4];"
                    : "=r"(a[mt][0]), "=r"(a[mt][1]), "=r"(a[mt][2]), "=r"(a[mt][3])
                    : "r"(addr));
            }
            unsigned bf[4][4];
            #pragma unroll
            for (int p = 0; p < 4; p++) {
                unsigned addr = (unsigned)__cvta_generic_to_shared(
                    Bbuf + (wn + p*16 + f_r)*HST + ks*16 + f_kh);
                asm volatile("ldmatrix.sync.aligned.m8n8.x4.shared.b16 {%0,%1,%2,%3}, [%4];"
                    : "=r"(bf[p][0]), "=r"(bf[p][1]), "=r"(bf[p][2]), "=r"(bf[p][3])
                    : "r"(addr));
            }
            #pragma unroll
            for (int nt = 0; nt < 8; nt++) {
                unsigned b0 = bf[nt >> 1][(nt & 1)];
                unsigned b1 = bf[nt >> 1][(nt & 1) + 2];
                #pragma unroll
                for (int mt = 0; mt < 2; mt++) {
                    asm volatile(
                        "mma.sync.aligned.m16n8k16.row.col.f32.f16.f16.f32 "
                        "{%0,%1,%2,%3}, {%4,%5,%6,%7}, {%8,%9}, {%0,%1,%2,%3};"
                        : "+f"(acc[mt][nt][0]), "+f"(acc[mt][nt][1]),
                          "+f"(acc[mt][nt][2]), "+f"(acc[mt][nt][3])
                        : "r"(a[mt][0]), "r"(a[mt][1]), "r"(a[mt][2]), "r"(a[mt][3]),
                          "r"(b0), "r"(b1));
                }
            }
        }
        buf ^= 1;
    }

    const int c_r = lane >> 2, c_c = (lane & 3) * 2;
    #pragma unroll
    for (int mt = 0; mt < 2; mt++) {
        #pragma unroll
        for (int nt = 0; nt < 8; nt++) {
            int row0 = m0 + wm + mt*16 + c_r;
            int col  = n0 + wn + nt*8 + c_c;
            float o0 = acc[mt][nt][0]*alpha, o1 = acc[mt][nt][1]*alpha;
            float o2 = acc[mt][nt][2]*alpha, o3 = acc[mt][nt][3]*alpha;
            if (bias) {
                float bx = bias[col], by = bias[col+1];
                o0 += bx; o1 += by; o2 += bx; o3 += by;
            }
            if (HOUT) {
                __half* Cb = (__half*)Cv + (size_t)blockIdx.z * strC;
                *(__half2*)(Cb + (size_t)row0*ldc + col)     = __floats2half2_rn(o0, o1);
                *(__half2*)(Cb + (size_t)(row0+8)*ldc + col) = __floats2half2_rn(o2, o3);
            } else {
                float* Cb = (float*)Cv + (size_t)blockIdx.z * strC;
                if (resid) {
                    float2 r0 = *(const float2*)(resid + (size_t)row0*ldc + col);
                    float2 r1 = *(const float2*)(resid + (size_t)(row0+8)*ldc + col);
                    o0 += r0.x; o1 += r0.y; o2 += r1.x; o3 += r1.y;
                }
                *(float2*)(Cb + (size_t)row0*ldc + col)     = make_float2(o0, o1);
                *(float2*)(Cb + (size_t)(row0+8)*ldc + col) = make_float2(o2, o3);
            }
        }
    }
}

// ---------------- row softmax: fp32 in -> fp16 out ----------------
__global__ void softmax_kernel(const float* __restrict__ s, __half* __restrict__ pout) {
    const float4* p = reinterpret_cast<const float4*>(s) + (size_t)blockIdx.x * (NTOK/4);
    __half2* po = reinterpret_cast<__half2*>(pout + (size_t)blockIdx.x * NTOK);
    int tid = threadIdx.x;

    float4 v[4];
    float m = -3.4e38f;
    #pragma unroll
    for (int t = 0; t < 4; t++) {
        v[t] = p[tid + t*256];
        m = fmaxf(m, fmaxf(fmaxf(v[t].x, v[t].y), fmaxf(v[t].z, v[t].w)));
    }
    __shared__ float red[256];
    red[tid] = m; __syncthreads();
    for (int o = 128; o > 0; o >>= 1) {
        if (tid < o) red[tid] = fmaxf(red[tid], red[tid+o]);
        __syncthreads();
    }
    m = red[0]; __syncthreads();

    float sum = 0.f;
    #pragma unroll
    for (int t = 0; t < 4; t++) {
        v[t].x = __expf(v[t].x - m); v[t].y = __expf(v[t].y - m);
        v[t].z = __expf(v[t].z - m); v[t].w = __expf(v[t].w - m);
        sum += v[t].x + v[t].y + v[t].z + v[t].w;
    }
    red[tid] = sum; __syncthreads();
    for (int o = 128; o > 0; o >>= 1) {
        if (tid < o) red[tid] += red[tid+o];
        __syncthreads();
    }
    float r = 1.f / red[0];
    #pragma unroll
    for (int t = 0; t < 4; t++) {
        int idx = tid + t*256;
        po[idx*2]   = __floats2half2_rn(v[t].x * r, v[t].y * r);
        po[idx*2+1] = __floats2half2_rn(v[t].z * r, v[t].w * r);
    }
}

// ---------------- launch ----------------
extern "C" void kernel_launch(void* const* d_in, const int* in_sizes, int n_in,
                              void* d_out, int out_size) {
    const float* x  = (const float*)d_in[0];
    const float* gs = (const float*)d_in[1];
    const float* gb = (const float*)d_in[2];
    const float* wq = (const float*)d_in[3];
    const float* bq = (const float*)d_in[4];
    const float* wk = (const float*)d_in[5];
    const float* bk = (const float*)d_in[6];
    const float* wv = (const float*)d_in[7];
    const float* bv = (const float*)d_in[8];
    const float* wo = (const float*)d_in[9];
    const float* bo = (const float*)d_in[10];
    float* out = (float*)d_out;

    __half *h, *qkv, *vth, *ao, *pp, *w16;
    float *s, *bqkv;
    cudaGetSymbolAddress((void**)&h,    g_h);
    cudaGetSymbolAddress((void**)&qkv,  g_qkv);
    cudaGetSymbolAddress((void**)&vth,  g_vth);
    cudaGetSymbolAddress((void**)&ao,   g_ao);
    cudaGetSymbolAddress((void**)&s,    g_s);
    cudaGetSymbolAddress((void**)&pp,   g_p);
    cudaGetSymbolAddress((void**)&w16,  g_w16);
    cudaGetSymbolAddress((void**)&bqkv, g_bqkv);

    __half* wqkvT = w16;                            // [3*CC][CC]
    __half* woT   = w16 + 3*(size_t)CC*CC;          // [CC][CC]

    const long long sNC  = (long long)NTOK * CC;
    const long long sNN  = (long long)NTOK * NTOK;
    const long long sQKV = (long long)NTOK * 3*CC;
    const int Mtot = Bb * NTOK;                      // 32768
    const float inv_sqrt_c = 0.044194173824159216f;  // 512^-0.5

    dim3 tb(32, 8);

    // 0) weight transposes -> fp16 (wq/wk/wv into packed sections), bias pack
    dim3 gtw(CC/32, CC/32, 1);
    transpose_f2h<<<gtw, tb>>>(wq, wqkvT,                       CC, CC);
    transpose_f2h<<<gtw, tb>>>(wk, wqkvT +   (size_t)CC*CC,     CC, CC);
    transpose_f2h<<<gtw, tb>>>(wv, wqkvT + 2*(size_t)CC*CC,     CC, CC);
    transpose_f2h<<<gtw, tb>>>(wo, woT,                         CC, CC);
    pack_bias<<<6, 256>>>(bq, bk, bv, bqkv);

    // 1) GroupNorm -> fp16 h
    gn_kernel<<<Bb*GG, 256>>>(x, gs, gb, h);

    // 2) fused QKV projection: [32768,512] @ [512,1536] -> packed qkv fp16
    dim3 gqkv(3*CC/128, Mtot/128, 1);
    hgemm<true><<<gqkv, 256>>>(h, CC, 0, wqkvT, CC, 0, qkv, 3*CC, 0,
                               bqkv, nullptr, 1.f, CC);

    // 3) V -> V^T fp16 per batch (v = qkv section 2, ldi = 1536)
    dim3 gtv(NTOK/32, CC/32, Bb);
    transpose_h2h<<<gtv, tb>>>(qkv + 2*CC, vth, NTOK, CC, 3*CC, sQKV, sNC);

    // 4) scores = alpha * Q @ K^T (fp16 in, fp32 out)
    dim3 gsc(NTOK/128, NTOK/128, Bb);
    hgemm<false><<<gsc, 256>>>(qkv, 3*CC, sQKV, qkv + CC, 3*CC, sQKV,
                               s, NTOK, sNN, nullptr, nullptr, inv_sqrt_c, CC);

    // 5) softmax: fp32 scores -> fp16 P
    softmax_kernel<<<Bb*NTOK, 256>>>(s, pp);

    // 6) attn @ V fp16 -> ao fp16
    dim3 gav(CC/128, NTOK/128, Bb);
    hgemm<true><<<gav, 256>>>(pp, NTOK, sNN, vth, NTOK, sNC,
                              ao, CC, sNC, nullptr, nullptr, 1.f, NTOK);

    // 7) output projection + bias + residual -> d_out (fp32)
    dim3 gout(CC/128, Mtot/128, 1);
    hgemm<false><<<gout, 256>>>(ao, CC, 0, woT, CC, 0, out, CC, 0,
                                bo, x, 1.f, CC);
}

// round 13
// speedup vs baseline: 4.4461x; 1.0349x over previous
#include <cuda_runtime.h>
#include <cuda_fp16.h>
#include <math.h>
#include <stdint.h>

#define Bb 8
#define CC 512
#define GG 32
#define CGc 16
#define NTOK 4096
#define EPSV 1e-5f

// ---------------- scratch (device globals; no runtime allocation) ----------------
__device__ __half g_h  [(size_t)Bb*NTOK*CC];          // GN output, fp16
__device__ __half g_qkv[(size_t)Bb*NTOK*3*CC];        // packed q|k|v, fp16
__device__ __half g_vth[(size_t)Bb*NTOK*CC];          // V^T per batch fp16 [CC][NTOK]
__device__ __half g_ao [(size_t)Bb*NTOK*CC];          // attention output fp16
__device__ __half g_s  [(size_t)Bb*NTOK*NTOK];        // fp16 raw scores (256 MB)
__device__ __half g_p  [(size_t)Bb*NTOK*NTOK];        // fp16 probabilities (256 MB)
__device__ __half g_w16[4*(size_t)CC*CC];             // wqkvT (3 sections) + woT, fp16
__device__ float  g_bqkv[3*CC];                       // packed biases

// ---------------- GroupNorm -> fp16 ----------------
__global__ void gn_kernel(const float* __restrict__ x,
                          const float* __restrict__ sc,
                          const float* __restrict__ bi,
                          __half* __restrict__ h) {
    int b = blockIdx.x / GG, g = blockIdx.x % GG;
    const float* xp = x + (size_t)b*NTOK*CC + g*CGc;
    __half*      hp = h + (size_t)b*NTOK*CC + g*CGc;
    int tid = threadIdx.x;

    float s = 0.f, ss = 0.f;
    for (int i = tid; i < NTOK*CGc; i += 256) {
        int n = i >> 4, c = i & 15;
        float v = xp[(size_t)n*CC + c];
        s += v; ss += v*v;
    }
    __shared__ float r1[256], r2[256];
    r1[tid] = s; r2[tid] = ss; __syncthreads();
    for (int o = 128; o > 0; o >>= 1) {
        if (tid < o) { r1[tid] += r1[tid+o]; r2[tid] += r2[tid+o]; }
        __syncthreads();
    }
    const float invn = 1.f / (float)(NTOK*CGc);
    float mean = r1[0] * invn;
    float var  = r2[0] * invn - mean*mean;
    float inv  = rsqrtf(var + EPSV);

    for (int i = tid; i < NTOK*CGc; i += 256) {
        int n = i >> 4, c = i & 15;
        float v = xp[(size_t)n*CC + c];
        hp[(size_t)n*CC + c] =
            __float2half((v - mean) * inv * sc[g*CGc + c] + bi[g*CGc + c]);
    }
}

// ---------------- transpose fp32 -> fp16: in[R][Cc] -> out[Cc][R] ----------------
__global__ void transpose_f2h(const float* __restrict__ in, __half* __restrict__ out,
                              int R, int Cc) {
    __shared__ float t[32][33];
    int r0 = blockIdx.x * 32, c0 = blockIdx.y * 32;
    int x = threadIdx.x, y = threadIdx.y;
    #pragma unroll
    for (int i = 0; i < 32; i += 8)
        t[y+i][x] = in[(size_t)(r0+y+i)*Cc + c0 + x];
    __syncthreads();
    #pragma unroll
    for (int i = 0; i < 32; i += 8)
        out[(size_t)(c0+y+i)*R + r0 + x] = __float2half(t[x][y+i]);
}

// ---------------- batched transpose fp16: in[R][ldi] -> out[Cc][R] ----------------
__global__ void transpose_h2h(const __half* __restrict__ in, __half* __restrict__ out,
                              int R, int Cc, int ldi,
                              long long sIn, long long sOut) {
    __shared__ __half t[32][34];
    int b = blockIdx.z;
    int r0 = blockIdx.x * 32, c0 = blockIdx.y * 32;
    const __half* ip = in  + (size_t)b*sIn;
    __half*       op = out + (size_t)b*sOut;
    int x = threadIdx.x, y = threadIdx.y;
    #pragma unroll
    for (int i = 0; i < 32; i += 8)
        t[y+i][x] = ip[(size_t)(r0+y+i)*ldi + c0 + x];
    __syncthreads();
    #pragma unroll
    for (int i = 0; i < 32; i += 8)
        op[(size_t)(c0+y+i)*R + r0 + x] = t[x][y+i];
}

// ---------------- bias pack ----------------
__global__ void pack_bias(const float* __restrict__ bq, const float* __restrict__ bk,
                          const float* __restrict__ bv, float* __restrict__ o) {
    int i = threadIdx.x + blockIdx.x * 256;
    if (i < CC)            o[i] = bq[i];
    else if (i < 2*CC)     o[i] = bk[i - CC];
    else if (i < 3*CC)     o[i] = bv[i - 2*CC];
}

// ---------------- fp16 tensor-core GEMM (m16n8k16) ----------------
// C[M,N] = alpha * A[M,K] @ Bt^T (+bias)(+resid); A [M][K] fp16 (lda), Bt [N][K]
// fp16 (ldbt). HOUT: C fp16, else fp32. resid only in fp32 path.
#define HST 40
#define HTSZ (128*HST)

template<bool HOUT>
__global__ __launch_bounds__(256)
void hgemm(const __half* __restrict__ A, int lda, long long strA,
           const __half* __restrict__ Bt, int ldbt, long long strB,
           void* __restrict__ Cv, int ldc, long long strC,
           const float* __restrict__ bias,
           const float* __restrict__ resid,
           float alpha, int K)
{
    __shared__ __half As[2*HTSZ];
    __shared__ __half Bs[2*HTSZ];

    const __half* Ab = A  + (size_t)blockIdx.z * strA;
    const __half* Bg = Bt + (size_t)blockIdx.z * strB;

    const int m0 = blockIdx.y * 128, n0 = blockIdx.x * 128;
    const int tid = threadIdx.x, lane = tid & 31, wid = tid >> 5;
    const int wm = (wid >> 1) * 32;
    const int wn = (wid & 1)  * 64;

    const int trow = tid >> 1, tch = (tid & 1) * 2;

    const __half* agp = Ab + (size_t)(m0 + trow) * lda  + tch*8;
    const __half* bgp = Bg + (size_t)(n0 + trow) * ldbt + tch*8;

    unsigned asp[2], bsp[2];
    #pragma unroll
    for (int c = 0; c < 2; c++) {
        asp[c] = (unsigned)__cvta_generic_to_shared(&As[trow*HST + (tch+c)*8]);
        bsp[c] = (unsigned)__cvta_generic_to_shared(&Bs[trow*HST + (tch+c)*8]);
    }
    const unsigned BUFB = HTSZ * 2;

    float acc[2][8][4];
    #pragma unroll
    for (int i = 0; i < 2; i++)
        #pragma unroll
        for (int j = 0; j < 8; j++)
            #pragma unroll
            for (int q = 0; q < 4; q++) acc[i][j][q] = 0.f;

    const int f_r  = (lane & 7) + ((lane >> 3) & 1) * 8;
    const int f_kh = ((lane >> 4) & 1) * 8;

    const int KIT = K / 32;

    #pragma unroll
    for (int c = 0; c < 2; c++) {
        asm volatile("cp.async.cg.shared.global [%0], [%1], 16;\n"
                     :: "r"(asp[c]), "l"(agp + c*8) : "memory");
        asm volatile("cp.async.cg.shared.global [%0], [%1], 16;\n"
                     :: "r"(bsp[c]), "l"(bgp + c*8) : "memory");
    }
    asm volatile("cp.async.commit_group;\n" ::: "memory");

    int buf = 0;
    for (int it = 0; it < KIT; ++it) {
        asm volatile("cp.async.wait_group 0;\n" ::: "memory");
        __syncthreads();

        if (it + 1 < KIT) {
            const __half* ag = agp + (size_t)(it+1)*32;
            const __half* bg = bgp + (size_t)(it+1)*32;
            unsigned ob = (unsigned)(buf ^ 1);
            #pragma unroll
            for (int c = 0; c < 2; c++) {
                asm volatile("cp.async.cg.shared.global [%0], [%1], 16;\n"
                             :: "r"(asp[c] + ob*BUFB), "l"(ag + c*8) : "memory");
                asm volatile("cp.async.cg.shared.global [%0], [%1], 16;\n"
                             :: "r"(bsp[c] + ob*BUFB), "l"(bg + c*8) : "memory");
            }
            asm volatile("cp.async.commit_group;\n" ::: "memory");
        }

        const __half* Abuf = As + buf*HTSZ;
        const __half* Bbuf = Bs + buf*HTSZ;

        #pragma unroll
        for (int ks = 0; ks < 2; ks++) {
            unsigned a[2][4];
            #pragma unroll
            for (int mt = 0; mt < 2; mt++) {
                unsigned addr = (unsigned)__cvta_generic_to_shared(
                    Abuf + (wm + mt*16 + f_r)*HST + ks*16 + f_kh);
                asm volatile("ldmatrix.sync.aligned.m8n8.x4.shared.b16 {%0,%1,%2,%3}, [%4];"
                    : "=r"(a[mt][0]), "=r"(a[mt][1]), "=r"(a[mt][2]), "=r"(a[mt][3])
                    : "r"(addr));
            }
            unsigned bf[4][4];
            #pragma unroll
            for (int p = 0; p < 4; p++) {
                unsigned addr = (unsigned)__cvta_generic_to_shared(
                    Bbuf + (wn + p*16 + f_r)*HST + ks*16 + f_kh);
                asm volatile("ldmatrix.sync.aligned.m8n8.x4.shared.b16 {%0,%1,%2,%3}, [%4];"
                    : "=r"(bf[p][0]), "=r"(bf[p][1]), "=r"(bf[p][2]), "=r"(bf[p][3])
                    : "r"(addr));
            }
            #pragma unroll
            for (int nt = 0; nt < 8; nt++) {
                unsigned b0 = bf[nt >> 1][(nt & 1)];
                unsigned b1 = bf[nt >> 1][(nt & 1) + 2];
                #pragma unroll
                for (int mt = 0; mt < 2; mt++) {
                    asm volatile(
                        "mma.sync.aligned.m16n8k16.row.col.f32.f16.f16.f32 "
                        "{%0,%1,%2,%3}, {%4,%5,%6,%7}, {%8,%9}, {%0,%1,%2,%3};"
                        : "+f"(acc[mt][nt][0]), "+f"(acc[mt][nt][1]),
                          "+f"(acc[mt][nt][2]), "+f"(acc[mt][nt][3])
                        : "r"(a[mt][0]), "r"(a[mt][1]), "r"(a[mt][2]), "r"(a[mt][3]),
                          "r"(b0), "r"(b1));
                }
            }
        }
        buf ^= 1;
    }

    const int c_r = lane >> 2, c_c = (lane & 3) * 2;
    #pragma unroll
    for (int mt = 0; mt < 2; mt++) {
        #pragma unroll
        for (int nt = 0; nt < 8; nt++) {
            int row0 = m0 + wm + mt*16 + c_r;
            int col  = n0 + wn + nt*8 + c_c;
            float o0 = acc[mt][nt][0]*alpha, o1 = acc[mt][nt][1]*alpha;
            float o2 = acc[mt][nt][2]*alpha, o3 = acc[mt][nt][3]*alpha;
            if (bias) {
                float bx = bias[col], by = bias[col+1];
                o0 += bx; o1 += by; o2 += bx; o3 += by;
            }
            if (HOUT) {
                __half* Cb = (__half*)Cv + (size_t)blockIdx.z * strC;
                *(__half2*)(Cb + (size_t)row0*ldc + col)     = __floats2half2_rn(o0, o1);
                *(__half2*)(Cb + (size_t)(row0+8)*ldc + col) = __floats2half2_rn(o2, o3);
            } else {
                float* Cb = (float*)Cv + (size_t)blockIdx.z * strC;
                if (resid) {
                    float2 r0 = *(const float2*)(resid + (size_t)row0*ldc + col);
                    float2 r1 = *(const float2*)(resid + (size_t)(row0+8)*ldc + col);
                    o0 += r0.x; o1 += r0.y; o2 += r1.x; o3 += r1.y;
                }
                *(float2*)(Cb + (size_t)row0*ldc + col)     = make_float2(o0, o1);
                *(float2*)(Cb + (size_t)(row0+8)*ldc + col) = make_float2(o2, o3);
            }
        }
    }
}

// ---------------- row softmax: fp16 in -> fp16 out (fp32 math) ----------------
__global__ void softmax_kernel(const __half* __restrict__ s, __half* __restrict__ pout) {
    const __half2* p = reinterpret_cast<const __half2*>(s) + (size_t)blockIdx.x * (NTOK/2);
    __half2* po = reinterpret_cast<__half2*>(pout) + (size_t)blockIdx.x * (NTOK/2);
    int tid = threadIdx.x;

    float2 v[8];
    float m = -3.4e38f;
    #pragma unroll
    for (int t = 0; t < 8; t++) {
        v[t] = __half22float2(p[tid + t*256]);
        m = fmaxf(m, fmaxf(v[t].x, v[t].y));
    }
    __shared__ float red[256];
    red[tid] = m; __syncthreads();
    for (int o = 128; o > 0; o >>= 1) {
        if (tid < o) red[tid] = fmaxf(red[tid], red[tid+o]);
        __syncthreads();
    }
    m = red[0]; __syncthreads();

    float sum = 0.f;
    #pragma unroll
    for (int t = 0; t < 8; t++) {
        v[t].x = __expf(v[t].x - m);
        v[t].y = __expf(v[t].y - m);
        sum += v[t].x + v[t].y;
    }
    red[tid] = sum; __syncthreads();
    for (int o = 128; o > 0; o >>= 1) {
        if (tid < o) red[tid] += red[tid+o];
        __syncthreads();
    }
    float r = 1.f / red[0];
    #pragma unroll
    for (int t = 0; t < 8; t++)
        po[tid + t*256] = __floats2half2_rn(v[t].x * r, v[t].y * r);
}

// ---------------- launch ----------------
extern "C" void kernel_launch(void* const* d_in, const int* in_sizes, int n_in,
                              void* d_out, int out_size) {
    const float* x  = (const float*)d_in[0];
    const float* gs = (const float*)d_in[1];
    const float* gb = (const float*)d_in[2];
    const float* wq = (const float*)d_in[3];
    const float* bq = (const float*)d_in[4];
    const float* wk = (const float*)d_in[5];
    const float* bk = (const float*)d_in[6];
    const float* wv = (const float*)d_in[7];
    const float* bv = (const float*)d_in[8];
    const float* wo = (const float*)d_in[9];
    const float* bo = (const float*)d_in[10];
    float* out = (float*)d_out;

    __half *h, *qkv, *vth, *ao, *sh, *pp, *w16;
    float *bqkv;
    cudaGetSymbolAddress((void**)&h,    g_h);
    cudaGetSymbolAddress((void**)&qkv,  g_qkv);
    cudaGetSymbolAddress((void**)&vth,  g_vth);
    cudaGetSymbolAddress((void**)&ao,   g_ao);
    cudaGetSymbolAddress((void**)&sh,   g_s);
    cudaGetSymbolAddress((void**)&pp,   g_p);
    cudaGetSymbolAddress((void**)&w16,  g_w16);
    cudaGetSymbolAddress((void**)&bqkv, g_bqkv);

    __half* wqkvT = w16;                            // [3*CC][CC]
    __half* woT   = w16 + 3*(size_t)CC*CC;          // [CC][CC]

    const long long sNC  = (long long)NTOK * CC;
    const long long sNN  = (long long)NTOK * NTOK;
    const long long sQKV = (long long)NTOK * 3*CC;
    const int Mtot = Bb * NTOK;                      // 32768
    const float inv_sqrt_c = 0.044194173824159216f;  // 512^-0.5

    dim3 tb(32, 8);

    // 0) weight transposes -> fp16 (wq/wk/wv into packed sections), bias pack
    dim3 gtw(CC/32, CC/32, 1);
    transpose_f2h<<<gtw, tb>>>(wq, wqkvT,                       CC, CC);
    transpose_f2h<<<gtw, tb>>>(wk, wqkvT +   (size_t)CC*CC,     CC, CC);
    transpose_f2h<<<gtw, tb>>>(wv, wqkvT + 2*(size_t)CC*CC,     CC, CC);
    transpose_f2h<<<gtw, tb>>>(wo, woT,                         CC, CC);
    pack_bias<<<6, 256>>>(bq, bk, bv, bqkv);

    // 1) GroupNorm -> fp16 h
    gn_kernel<<<Bb*GG, 256>>>(x, gs, gb, h);

    // 2) fused QKV projection: [32768,512] @ [512,1536] -> packed qkv fp16
    dim3 gqkv(3*CC/128, Mtot/128, 1);
    hgemm<true><<<gqkv, 256>>>(h, CC, 0, wqkvT, CC, 0, qkv, 3*CC, 0,
                               bqkv, nullptr, 1.f, CC);

    // 3) V -> V^T fp16 per batch (v = qkv section 2, ldi = 1536)
    dim3 gtv(NTOK/32, CC/32, Bb);
    transpose_h2h<<<gtv, tb>>>(qkv + 2*CC, vth, NTOK, CC, 3*CC, sQKV, sNC);

    // 4) scores = alpha * Q @ K^T (fp16 in, fp16 out; alpha in epilogue)
    dim3 gsc(NTOK/128, NTOK/128, Bb);
    hgemm<true><<<gsc, 256>>>(qkv, 3*CC, sQKV, qkv + CC, 3*CC, sQKV,
                              sh, NTOK, sNN, nullptr, nullptr, inv_sqrt_c, CC);

    // 5) softmax: fp16 scores -> fp16 P (fp32 math)
    softmax_kernel<<<Bb*NTOK, 256>>>(sh, pp);

    // 6) attn @ V fp16 -> ao fp16
    dim3 gav(CC/128, NTOK/128, Bb);
    hgemm<true><<<gav, 256>>>(pp, NTOK, sNN, vth, NTOK, sNC,
                              ao, CC, sNC, nullptr, nullptr, 1.f, NTOK);

    // 7) output projection + bias + residual -> d_out (fp32)
    dim3 gout(CC/128, Mtot/128, 1);
    hgemm<false><<<gout, 256>>>(ao, CC, 0, woT, CC, 0, out, CC, 0,
                                bo, x, 1.f, CC);
}

// round 14
// speedup vs baseline: 4.4925x; 1.0104x over previous
#include <cuda_runtime.h>
#include <cuda_fp16.h>
#include <math.h>
#include <stdint.h>

#define Bb 8
#define CC 512
#define GG 32
#define CGc 16
#define NTOK 4096
#define EPSV 1e-5f

// ---------------- scratch (device globals; no runtime allocation) ----------------
__device__ __half g_h  [(size_t)Bb*NTOK*CC];          // GN output, fp16
__device__ __half g_qkv[(size_t)Bb*NTOK*3*CC];        // packed q|k|v, fp16
__device__ __half g_vth[(size_t)Bb*NTOK*CC];          // V^T per batch fp16 [CC][NTOK]
__device__ __half g_ao [(size_t)Bb*NTOK*CC];          // attention output fp16
__device__ __half g_s  [(size_t)Bb*NTOK*NTOK];        // fp16 raw scores (256 MB)
__device__ __half g_p  [(size_t)Bb*NTOK*NTOK];        // fp16 probabilities (256 MB)
__device__ __half g_w16[4*(size_t)CC*CC];             // wqkvT (3 sections) + woT, fp16
__device__ float  g_bqkv[3*CC];                       // packed biases

// ---------------- GroupNorm -> fp16 ----------------
__global__ void gn_kernel(const float* __restrict__ x,
                          const float* __restrict__ sc,
                          const float* __restrict__ bi,
                          __half* __restrict__ h) {
    int b = blockIdx.x / GG, g = blockIdx.x % GG;
    const float* xp = x + (size_t)b*NTOK*CC + g*CGc;
    __half*      hp = h + (size_t)b*NTOK*CC + g*CGc;
    int tid = threadIdx.x;

    float s = 0.f, ss = 0.f;
    for (int i = tid; i < NTOK*CGc; i += 256) {
        int n = i >> 4, c = i & 15;
        float v = xp[(size_t)n*CC + c];
        s += v; ss += v*v;
    }
    __shared__ float r1[256], r2[256];
    r1[tid] = s; r2[tid] = ss; __syncthreads();
    for (int o = 128; o > 0; o >>= 1) {
        if (tid < o) { r1[tid] += r1[tid+o]; r2[tid] += r2[tid+o]; }
        __syncthreads();
    }
    const float invn = 1.f / (float)(NTOK*CGc);
    float mean = r1[0] * invn;
    float var  = r2[0] * invn - mean*mean;
    float inv  = rsqrtf(var + EPSV);

    for (int i = tid; i < NTOK*CGc; i += 256) {
        int n = i >> 4, c = i & 15;
        float v = xp[(size_t)n*CC + c];
        hp[(size_t)n*CC + c] =
            __float2half((v - mean) * inv * sc[g*CGc + c] + bi[g*CGc + c]);
    }
}

// ---------------- transpose fp32 -> fp16: in[R][Cc] -> out[Cc][R] ----------------
__global__ void transpose_f2h(const float* __restrict__ in, __half* __restrict__ out,
                              int R, int Cc) {
    __shared__ float t[32][33];
    int r0 = blockIdx.x * 32, c0 = blockIdx.y * 32;
    int x = threadIdx.x, y = threadIdx.y;
    #pragma unroll
    for (int i = 0; i < 32; i += 8)
        t[y+i][x] = in[(size_t)(r0+y+i)*Cc + c0 + x];
    __syncthreads();
    #pragma unroll
    for (int i = 0; i < 32; i += 8)
        out[(size_t)(c0+y+i)*R + r0 + x] = __float2half(t[x][y+i]);
}

// ---------------- batched transpose fp16: in[R][ldi] -> out[Cc][R] ----------------
__global__ void transpose_h2h(const __half* __restrict__ in, __half* __restrict__ out,
                              int R, int Cc, int ldi,
                              long long sIn, long long sOut) {
    __shared__ __half t[32][34];
    int b = blockIdx.z;
    int r0 = blockIdx.x * 32, c0 = blockIdx.y * 32;
    const __half* ip = in  + (size_t)b*sIn;
    __half*       op = out + (size_t)b*sOut;
    int x = threadIdx.x, y = threadIdx.y;
    #pragma unroll
    for (int i = 0; i < 32; i += 8)
        t[y+i][x] = ip[(size_t)(r0+y+i)*ldi + c0 + x];
    __syncthreads();
    #pragma unroll
    for (int i = 0; i < 32; i += 8)
        op[(size_t)(c0+y+i)*R + r0 + x] = t[x][y+i];
}

// ---------------- bias pack ----------------
__global__ void pack_bias(const float* __restrict__ bq, const float* __restrict__ bk,
                          const float* __restrict__ bv, float* __restrict__ o) {
    int i = threadIdx.x + blockIdx.x * 256;
    if (i < CC)            o[i] = bq[i];
    else if (i < 2*CC)     o[i] = bk[i - CC];
    else if (i < 3*CC)     o[i] = bv[i - 2*CC];
}

// ---------------- fp16 tensor-core GEMM (m16n8k16) ----------------
// C[M,N] = alpha * A[M,K] @ Bt^T (+bias)(+resid); A [M][K] fp16 (lda), Bt [N][K]
// fp16 (ldbt). HOUT: C fp16, else fp32. resid only in fp32 path.
#define HST 40
#define HTSZ (128*HST)

template<bool HOUT>
__global__ __launch_bounds__(256)
void hgemm(const __half* __restrict__ A, int lda, long long strA,
           const __half* __restrict__ Bt, int ldbt, long long strB,
           void* __restrict__ Cv, int ldc, long long strC,
           const float* __restrict__ bias,
           const float* __restrict__ resid,
           float alpha, int K)
{
    __shared__ __half As[2*HTSZ];
    __shared__ __half Bs[2*HTSZ];

    const __half* Ab = A  + (size_t)blockIdx.z * strA;
    const __half* Bg = Bt + (size_t)blockIdx.z * strB;

    const int m0 = blockIdx.y * 128, n0 = blockIdx.x * 128;
    const int tid = threadIdx.x, lane = tid & 31, wid = tid >> 5;
    const int wm = (wid >> 1) * 32;
    const int wn = (wid & 1)  * 64;

    const int trow = tid >> 1, tch = (tid & 1) * 2;

    const __half* agp = Ab + (size_t)(m0 + trow) * lda  + tch*8;
    const __half* bgp = Bg + (size_t)(n0 + trow) * ldbt + tch*8;

    unsigned asp[2], bsp[2];
    #pragma unroll
    for (int c = 0; c < 2; c++) {
        asp[c] = (unsigned)__cvta_generic_to_shared(&As[trow*HST + (tch+c)*8]);
        bsp[c] = (unsigned)__cvta_generic_to_shared(&Bs[trow*HST + (tch+c)*8]);
    }
    const unsigned BUFB = HTSZ * 2;

    float acc[2][8][4];
    #pragma unroll
    for (int i = 0; i < 2; i++)
        #pragma unroll
        for (int j = 0; j < 8; j++)
            #pragma unroll
            for (int q = 0; q < 4; q++) acc[i][j][q] = 0.f;

    const int f_r  = (lane & 7) + ((lane >> 3) & 1) * 8;
    const int f_kh = ((lane >> 4) & 1) * 8;

    const int KIT = K / 32;

    #pragma unroll
    for (int c = 0; c < 2; c++) {
        asm volatile("cp.async.cg.shared.global [%0], [%1], 16;\n"
                     :: "r"(asp[c]), "l"(agp + c*8) : "memory");
        asm volatile("cp.async.cg.shared.global [%0], [%1], 16;\n"
                     :: "r"(bsp[c]), "l"(bgp + c*8) : "memory");
    }
    asm volatile("cp.async.commit_group;\n" ::: "memory");

    int buf = 0;
    for (int it = 0; it < KIT; ++it) {
        asm volatile("cp.async.wait_group 0;\n" ::: "memory");
        __syncthreads();

        if (it + 1 < KIT) {
            const __half* ag = agp + (size_t)(it+1)*32;
            const __half* bg = bgp + (size_t)(it+1)*32;
            unsigned ob = (unsigned)(buf ^ 1);
            #pragma unroll
            for (int c = 0; c < 2; c++) {
                asm volatile("cp.async.cg.shared.global [%0], [%1], 16;\n"
                             :: "r"(asp[c] + ob*BUFB), "l"(ag + c*8) : "memory");
                asm volatile("cp.async.cg.shared.global [%0], [%1], 16;\n"
                             :: "r"(bsp[c] + ob*BUFB), "l"(bg + c*8) : "memory");
            }
            asm volatile("cp.async.commit_group;\n" ::: "memory");
        }

        const __half* Abuf = As + buf*HTSZ;
        const __half* Bbuf = Bs + buf*HTSZ;

        #pragma unroll
        for (int ks = 0; ks < 2; ks++) {
            unsigned a[2][4];
            #pragma unroll
            for (int mt = 0; mt < 2; mt++) {
                unsigned addr = (unsigned)__cvta_generic_to_shared(
                    Abuf + (wm + mt*16 + f_r)*HST + ks*16 + f_kh);
                asm volatile("ldmatrix.sync.aligned.m8n8.x4.shared.b16 {%0,%1,%2,%3}, [%4];"
                    : "=r"(a[mt][0]), "=r"(a[mt][1]), "=r"(a[mt][2]), "=r"(a[mt][3])
                    : "r"(addr));
            }
            unsigned bf[4][4];
            #pragma unroll
            for (int p = 0; p < 4; p++) {
                unsigned addr = (unsigned)__cvta_generic_to_shared(
                    Bbuf + (wn + p*16 + f_r)*HST + ks*16 + f_kh);
                asm volatile("ldmatrix.sync.aligned.m8n8.x4.shared.b16 {%0,%1,%2,%3}, [%4];"
                    : "=r"(bf[p][0]), "=r"(bf[p][1]), "=r"(bf[p][2]), "=r"(bf[p][3])
                    : "r"(addr));
            }
            #pragma unroll
            for (int nt = 0; nt < 8; nt++) {
                unsigned b0 = bf[nt >> 1][(nt & 1)];
                unsigned b1 = bf[nt >> 1][(nt & 1) + 2];
                #pragma unroll
                for (int mt = 0; mt < 2; mt++) {
                    asm volatile(
                        "mma.sync.aligned.m16n8k16.row.col.f32.f16.f16.f32 "
                        "{%0,%1,%2,%3}, {%4,%5,%6,%7}, {%8,%9}, {%0,%1,%2,%3};"
                        : "+f"(acc[mt][nt][0]), "+f"(acc[mt][nt][1]),
                          "+f"(acc[mt][nt][2]), "+f"(acc[mt][nt][3])
                        : "r"(a[mt][0]), "r"(a[mt][1]), "r"(a[mt][2]), "r"(a[mt][3]),
                          "r"(b0), "r"(b1));
                }
            }
        }
        buf ^= 1;
    }

    const int c_r = lane >> 2, c_c = (lane & 3) * 2;
    #pragma unroll
    for (int mt = 0; mt < 2; mt++) {
        #pragma unroll
        for (int nt = 0; nt < 8; nt++) {
            int row0 = m0 + wm + mt*16 + c_r;
            int col  = n0 + wn + nt*8 + c_c;
            float o0 = acc[mt][nt][0]*alpha, o1 = acc[mt][nt][1]*alpha;
            float o2 = acc[mt][nt][2]*alpha, o3 = acc[mt][nt][3]*alpha;
            if (bias) {
                float bx = bias[col], by = bias[col+1];
                o0 += bx; o1 += by; o2 += bx; o3 += by;
            }
            if (HOUT) {
                __half* Cb = (__half*)Cv + (size_t)blockIdx.z * strC;
                *(__half2*)(Cb + (size_t)row0*ldc + col)     = __floats2half2_rn(o0, o1);
                *(__half2*)(Cb + (size_t)(row0+8)*ldc + col) = __floats2half2_rn(o2, o3);
            } else {
                float* Cb = (float*)Cv + (size_t)blockIdx.z * strC;
                if (resid) {
                    float2 r0 = *(const float2*)(resid + (size_t)row0*ldc + col);
                    float2 r1 = *(const float2*)(resid + (size_t)(row0+8)*ldc + col);
                    o0 += r0.x; o1 += r0.y; o2 += r1.x; o3 += r1.y;
                }
                *(float2*)(Cb + (size_t)row0*ldc + col)     = make_float2(o0, o1);
                *(float2*)(Cb + (size_t)(row0+8)*ldc + col) = make_float2(o2, o3);
            }
        }
    }
}

// ---------------- row softmax: fp16 in -> fp16 out, half2 math + f16x2 MUFU ----------------
__global__ void softmax_kernel(const __half* __restrict__ s, __half* __restrict__ pout) {
    const __half2* p = reinterpret_cast<const __half2*>(s) + (size_t)blockIdx.x * (NTOK/2);
    __half2* po = reinterpret_cast<__half2*>(pout) + (size_t)blockIdx.x * (NTOK/2);
    const int tid = threadIdx.x, lane = tid & 31, wid = tid >> 5;

    __half2 v[8];
    #pragma unroll
    for (int t = 0; t < 8; t++) v[t] = p[tid + t*256];

    // ---- row max (half2 domain, shuffle + 8-slot smem) ----
    __half2 m2 = v[0];
    #pragma unroll
    for (int t = 1; t < 8; t++) m2 = __hmax2(m2, v[t]);
    #pragma unroll
    for (int o = 16; o > 0; o >>= 1) {
        unsigned mu = *(unsigned*)&m2;
        unsigned ou = __shfl_xor_sync(0xffffffffu, mu, o);
        m2 = __hmax2(m2, *(__half2*)&ou);
    }
    __shared__ __half2 mred[8];
    __shared__ float   sred[8];
    if (lane == 0) mred[wid] = m2;
    __syncthreads();
    m2 = mred[0];
    #pragma unroll
    for (int w = 1; w < 8; w++) m2 = __hmax2(m2, mred[w]);
    __half mm = __hmax(__low2half(m2), __high2half(m2));
    m2 = __half2half2(mm);

    // ---- exp via ex2.approx.f16x2 (2 exps per MUFU issue) ----
    const __half2 l2e = __float2half2_rn(1.44269504f);
    float sum = 0.f;
    #pragma unroll
    for (int t = 0; t < 8; t++) {
        __half2 xl = __hmul2(__hsub2(v[t], m2), l2e);
        unsigned xu = *(unsigned*)&xl, eu;
        asm("ex2.approx.f16x2 %0, %1;" : "=r"(eu) : "r"(xu));
        v[t] = *(__half2*)&eu;
        float2 f = __half22float2(v[t]);
        sum += f.x + f.y;
    }

    // ---- row sum (fp32, shuffle + 8-slot smem) ----
    #pragma unroll
    for (int o = 16; o > 0; o >>= 1)
        sum += __shfl_xor_sync(0xffffffffu, sum, o);
    if (lane == 0) sred[wid] = sum;
    __syncthreads();
    float tot = 0.f;
    #pragma unroll
    for (int w = 0; w < 8; w++) tot += sred[w];
    __half2 r2 = __float2half2_rn(1.f / tot);

    #pragma unroll
    for (int t = 0; t < 8; t++)
        po[tid + t*256] = __hmul2(v[t], r2);
}

// ---------------- launch ----------------
extern "C" void kernel_launch(void* const* d_in, const int* in_sizes, int n_in,
                              void* d_out, int out_size) {
    const float* x  = (const float*)d_in[0];
    const float* gs = (const float*)d_in[1];
    const float* gb = (const float*)d_in[2];
    const float* wq = (const float*)d_in[3];
    const float* bq = (const float*)d_in[4];
    const float* wk = (const float*)d_in[5];
    const float* bk = (const float*)d_in[6];
    const float* wv = (const float*)d_in[7];
    const float* bv = (const float*)d_in[8];
    const float* wo = (const float*)d_in[9];
    const float* bo = (const float*)d_in[10];
    float* out = (float*)d_out;

    __half *h, *qkv, *vth, *ao, *sh, *pp, *w16;
    float *bqkv;
    cudaGetSymbolAddress((void**)&h,    g_h);
    cudaGetSymbolAddress((void**)&qkv,  g_qkv);
    cudaGetSymbolAddress((void**)&vth,  g_vth);
    cudaGetSymbolAddress((void**)&ao,   g_ao);
    cudaGetSymbolAddress((void**)&sh,   g_s);
    cudaGetSymbolAddress((void**)&pp,   g_p);
    cudaGetSymbolAddress((void**)&w16,  g_w16);
    cudaGetSymbolAddress((void**)&bqkv, g_bqkv);

    __half* wqkvT = w16;                            // [3*CC][CC]
    __half* woT   = w16 + 3*(size_t)CC*CC;          // [CC][CC]

    const long long sNC  = (long long)NTOK * CC;
    const long long sNN  = (long long)NTOK * NTOK;
    const long long sQKV = (long long)NTOK * 3*CC;
    const int Mtot = Bb * NTOK;                      // 32768
    const float inv_sqrt_c = 0.044194173824159216f;  // 512^-0.5

    dim3 tb(32, 8);

    // 0) weight transposes -> fp16 (wq/wk/wv into packed sections), bias pack
    dim3 gtw(CC/32, CC/32, 1);
    transpose_f2h<<<gtw, tb>>>(wq, wqkvT,                       CC, CC);
    transpose_f2h<<<gtw, tb>>>(wk, wqkvT +   (size_t)CC*CC,     CC, CC);
    transpose_f2h<<<gtw, tb>>>(wv, wqkvT + 2*(size_t)CC*CC,     CC, CC);
    transpose_f2h<<<gtw, tb>>>(wo, woT,                         CC, CC);
    pack_bias<<<6, 256>>>(bq, bk, bv, bqkv);

    // 1) GroupNorm -> fp16 h
    gn_kernel<<<Bb*GG, 256>>>(x, gs, gb, h);

    // 2) fused QKV projection: [32768,512] @ [512,1536] -> packed qkv fp16
    dim3 gqkv(3*CC/128, Mtot/128, 1);
    hgemm<true><<<gqkv, 256>>>(h, CC, 0, wqkvT, CC, 0, qkv, 3*CC, 0,
                               bqkv, nullptr, 1.f, CC);

    // 3) V -> V^T fp16 per batch (v = qkv section 2, ldi = 1536)
    dim3 gtv(NTOK/32, CC/32, Bb);
    transpose_h2h<<<gtv, tb>>>(qkv + 2*CC, vth, NTOK, CC, 3*CC, sQKV, sNC);

    // 4) scores = alpha * Q @ K^T (fp16 in, fp16 out; alpha in epilogue)
    dim3 gsc(NTOK/128, NTOK/128, Bb);
    hgemm<true><<<gsc, 256>>>(qkv, 3*CC, sQKV, qkv + CC, 3*CC, sQKV,
                              sh, NTOK, sNN, nullptr, nullptr, inv_sqrt_c, CC);

    // 5) softmax: fp16 scores -> fp16 P (half2 + f16x2 MUFU)
    softmax_kernel<<<Bb*NTOK, 256>>>(sh, pp);

    // 6) attn @ V fp16 -> ao fp16
    dim3 gav(CC/128, NTOK/128, Bb);
    hgemm<true><<<gav, 256>>>(pp, NTOK, sNN, vth, NTOK, sNC,
                              ao, CC, sNC, nullptr, nullptr, 1.f, NTOK);

    // 7) output projection + bias + residual -> d_out (fp32)
    dim3 gout(CC/128, Mtot/128, 1);
    hgemm<false><<<gout, 256>>>(ao, CC, 0, woT, CC, 0, out, CC, 0,
                                bo, x, 1.f, CC);
}